// round 14
// baseline (speedup 1.0000x reference)
#include <cuda_runtime.h>
#include <cuda_fp16.h>
#include <math.h>
#include <stdint.h>

#define NN 32
#define VV 25
#define TT 64
#define RTOT (NN*VV*TT)   /* 51200 */

// ------------------------- scratch (device globals) -------------------------
__device__ float g_bufB[(size_t)RTOT * 512];
__device__ float g_h   [(size_t)RTOT * 256];
__device__ float g_y1  [(size_t)RTOT * 256];
__device__ float g_y2  [(size_t)RTOT * 256];
__device__ float g_z2  [(size_t)RTOT * 256];
__device__ float g_atts[NN*VV*VV*3];
__device__ float g_attf[NN*TT*TT*2];   // transposed layout [n][q][t][s]
__device__ float g_attb[NN*TT*TT*2];
__device__ float g_ps  [96*625];
__device__ float g_pt  [128*64*64];
// fp16 activation buffers (16B-aligned for cp.async)
__device__ __align__(128) __half g_ah [(size_t)RTOT * 1024];
__device__ __align__(128) __half g_xh [(size_t)RTOT * 256];
__device__ __align__(128) __half g_y1h[(size_t)RTOT * 256];
__device__ __align__(128) __half g_y2h[(size_t)RTOT * 256];
__device__ __align__(128) __half g_z2h[(size_t)RTOT * 256];
#define WTOT 1277952
__device__ __align__(128) __half g_wh[WTOT];
__device__ __align__(128) __half g_wl[WTOT];
#define OFF_QKS 0         /* K=256  N=384  */
#define OFF_WOS 98304     /* K=768  N=256  */
#define OFF_FFS 294912    /* K=256  N=256  */
#define OFF_QKT 360448    /* K=256  N=512  */
#define OFF_WOT 491520    /* K=1024 N=256  */
#define OFF_FFT 753664    /* K=256  N=256  */
#define OFF_CNV 819200    /* K=1792 N=256  */

__device__ __forceinline__ float gelu_f(float x) {
    return 0.5f * x * (1.0f + erff(x * 0.7071067811865475f));
}
__device__ __forceinline__ uint32_t packh2(float a, float b) {
    __half2 h = __floats2half2_rn(a, b);
    return *(uint32_t*)&h;
}
__device__ __forceinline__ uint32_t smem_u32(const void* p) {
    uint32_t a;
    asm("{ .reg .u64 t; cvta.to.shared.u64 t, %1; cvt.u32.u64 %0, t; }" : "=r"(a) : "l"(p));
    return a;
}
__device__ __forceinline__ void ldm4(uint32_t &r0, uint32_t &r1, uint32_t &r2,
                                     uint32_t &r3, uint32_t a) {
    asm volatile("ldmatrix.sync.aligned.m8n8.x4.shared.b16 {%0,%1,%2,%3}, [%4];"
        : "=r"(r0), "=r"(r1), "=r"(r2), "=r"(r3) : "r"(a));
}
__device__ __forceinline__ void mma16816h(float* c, const uint32_t* a, const uint32_t* b) {
    asm volatile(
        "mma.sync.aligned.m16n8k16.row.col.f32.f16.f16.f32 "
        "{%0,%1,%2,%3}, {%4,%5,%6,%7}, {%8,%9}, {%0,%1,%2,%3};"
        : "+f"(c[0]), "+f"(c[1]), "+f"(c[2]), "+f"(c[3])
        : "r"(a[0]), "r"(a[1]), "r"(a[2]), "r"(a[3]), "r"(b[0]), "r"(b[1]));
}
__device__ __forceinline__ void cpa16(uint32_t dst, const void* src) {
    asm volatile("cp.async.cg.shared.global [%0], [%1], 16;" :: "r"(dst), "l"(src));
}
__device__ __forceinline__ void cpa16z(uint32_t dst, const void* src, int sz) {
    asm volatile("cp.async.cg.shared.global [%0], [%1], 16, %2;" :: "r"(dst), "l"(src), "r"(sz));
}
#define CPA_COMMIT() asm volatile("cp.async.commit_group;" ::: "memory")
#define CPA_WAIT1() asm volatile("cp.async.wait_group 1;" ::: "memory")
#define CPA_WAIT0() asm volatile("cp.async.wait_group 0;" ::: "memory")

// smem swizzle for 128B rows (64 fp16): 16B chunk ch of row r at (ch ^ (r&7))*16
#define SWZ8(row, ch) ((uint32_t)((row) * 128 + (((ch) ^ ((row) & 7)) << 4)))

// ==== fp16 HMMA GEMM: 128x128 tile, warp tile 64x32, k-chunk 64, 2-stage ====
// C[M,N] = A[M,K](fp16) @ (Bh+Bl)[K,N] + bias; B stored [N][K].
// stage 48KB: A(16K) Bh(16K) Bl(16K); 2 stages = 96KB, 2 CTA/SM.
#define GSM (2*49152)
__global__ __launch_bounds__(256, 2) void gemm_h(
        const __half* __restrict__ A, const __half* __restrict__ Bh,
        const __half* __restrict__ Bl, const float* __restrict__ bias,
        float* __restrict__ C, int M, int N, int K) {
    extern __shared__ char sm[];
    const uint32_t sbase = smem_u32(sm);
    const int tid = threadIdx.x, lane = tid & 31, w = tid >> 5;
    const int wm = w & 1, wn = w >> 1;     // warp tile: 64 rows x 32 cols
    const int bm = blockIdx.y << 7, bn = blockIdx.x << 7;
    float acc[4][4][4];
#pragma unroll
    for (int i = 0; i < 4; i++)
#pragma unroll
        for (int j = 0; j < 4; j++)
#pragma unroll
            for (int q = 0; q < 4; q++) acc[i][j][q] = 0.f;
    const int nch = K >> 6;

    auto load_stage = [&](int c) {
        uint32_t st = sbase + (c & 1) * 49152;
        const int k0 = c << 6;
#pragma unroll
        for (int j = 0; j < 4; j++) {
            int f = j * 256 + tid;
            int row = f >> 3, ch = f & 7;
            uint32_t off = SWZ8(row, ch);
            cpa16(st + off,         A  + (size_t)(bm + row) * K + k0 + ch * 8);
            cpa16(st + 16384 + off, Bh + (size_t)(bn + row) * K + k0 + ch * 8);
            cpa16(st + 32768 + off, Bl + (size_t)(bn + row) * K + k0 + ch * 8);
        }
        CPA_COMMIT();
    };
    load_stage(0);
    for (int c = 0; c < nch; c++) {
        if (c + 1 < nch) { load_stage(c + 1); CPA_WAIT1(); }
        else CPA_WAIT0();
        __syncthreads();
        const uint32_t sA = sbase + (c & 1) * 49152;
        const uint32_t sBh = sA + 16384, sBl = sA + 32768;
#pragma unroll
        for (int kk = 0; kk < 4; kk++) {
            uint32_t af[4][4];
            const int arow = wm * 64 + (lane & 15);
            const int achunk = kk * 2 + (lane >> 4);
#pragma unroll
            for (int mi = 0; mi < 4; mi++) {
                int row = arow + mi * 16;
                ldm4(af[mi][0], af[mi][1], af[mi][2], af[mi][3], sA + SWZ8(row, achunk));
            }
            const int bchunk = kk * 2 + ((lane >> 3) & 1);
            uint32_t bh[4][2], bl[4][2];
#pragma unroll
            for (int ng = 0; ng < 2; ng++) {
                int brow = wn * 32 + ng * 16 + ((lane & 16) >> 1) + (lane & 7);
                ldm4(bh[2*ng][0], bh[2*ng][1], bh[2*ng+1][0], bh[2*ng+1][1],
                     sBh + SWZ8(brow, bchunk));
                ldm4(bl[2*ng][0], bl[2*ng][1], bl[2*ng+1][0], bl[2*ng+1][1],
                     sBl + SWZ8(brow, bchunk));
            }
#pragma unroll
            for (int mi = 0; mi < 4; mi++)
#pragma unroll
                for (int nf = 0; nf < 4; nf++)
                    mma16816h(acc[mi][nf], af[mi], bh[nf]);
#pragma unroll
            for (int mi = 0; mi < 4; mi++)
#pragma unroll
                for (int nf = 0; nf < 4; nf++)
                    mma16816h(acc[mi][nf], af[mi], bl[nf]);
        }
        __syncthreads();
    }
    const int gid = lane >> 2, tig = lane & 3;
#pragma unroll
    for (int mi = 0; mi < 4; mi++)
#pragma unroll
        for (int nf = 0; nf < 4; nf++) {
            int col = bn + wn * 32 + nf * 8 + tig * 2;
            float b0v = bias[col], b1v = bias[col + 1];
            int r0 = bm + wm * 64 + mi * 16 + gid;
            *(float2*)(C + (size_t)r0 * N + col) =
                make_float2(acc[mi][nf][0] + b0v, acc[mi][nf][1] + b1v);
            *(float2*)(C + (size_t)(r0 + 8) * N + col) =
                make_float2(acc[mi][nf][2] + b0v, acc[mi][nf][3] + b1v);
        }
}

// ===== conv (implicit im2col) fp16 HMMA: K=1792, warp tile 64x32 ============
__global__ __launch_bounds__(256, 2) void conv_h(
        const __half* __restrict__ Z, const __half* __restrict__ Bh,
        const __half* __restrict__ Bl, const float* __restrict__ bias,
        float* __restrict__ C) {
    const int N = 256, K = 1792;
    extern __shared__ char sm[];
    const uint32_t sbase = smem_u32(sm);
    const int tid = threadIdx.x, lane = tid & 31, w = tid >> 5;
    const int wm = w & 1, wn = w >> 1;
    const int bm = blockIdx.y << 7, bn = blockIdx.x << 7;
    float acc[4][4][4];
#pragma unroll
    for (int i = 0; i < 4; i++)
#pragma unroll
        for (int j = 0; j < 4; j++)
#pragma unroll
            for (int q = 0; q < 4; q++) acc[i][j][q] = 0.f;
    const int nch = K >> 6;   // 28

    auto load_stage = [&](int c) {
        uint32_t st = sbase + (c & 1) * 49152;
        const int k0 = c << 6;
        const int dt = (k0 >> 8) - 3;
        const int iio = k0 & 255;
#pragma unroll
        for (int j = 0; j < 4; j++) {
            int f = j * 256 + tid;
            int row = f >> 3, ch = f & 7;
            uint32_t off = SWZ8(row, ch);
            int grow = bm + row;
            int t = (grow / VV) % TT;
            int tt = t + dt;
            int ok = (tt >= 0 && tt < TT);
            size_t srcoff = ok ? ((size_t)grow + (size_t)dt * VV) * 256 + iio + ch * 8 : 0;
            cpa16z(st + off, Z + srcoff, ok ? 16 : 0);
            cpa16(st + 16384 + off, Bh + (size_t)(bn + row) * K + k0 + ch * 8);
            cpa16(st + 32768 + off, Bl + (size_t)(bn + row) * K + k0 + ch * 8);
        }
        CPA_COMMIT();
    };
    load_stage(0);
    for (int c = 0; c < nch; c++) {
        if (c + 1 < nch) { load_stage(c + 1); CPA_WAIT1(); }
        else CPA_WAIT0();
        __syncthreads();
        const uint32_t sA = sbase + (c & 1) * 49152;
        const uint32_t sBh = sA + 16384, sBl = sA + 32768;
#pragma unroll
        for (int kk = 0; kk < 4; kk++) {
            uint32_t af[4][4];
            const int arow = wm * 64 + (lane & 15);
            const int achunk = kk * 2 + (lane >> 4);
#pragma unroll
            for (int mi = 0; mi < 4; mi++) {
                int row = arow + mi * 16;
                ldm4(af[mi][0], af[mi][1], af[mi][2], af[mi][3], sA + SWZ8(row, achunk));
            }
            const int bchunk = kk * 2 + ((lane >> 3) & 1);
            uint32_t bh[4][2], bl[4][2];
#pragma unroll
            for (int ng = 0; ng < 2; ng++) {
                int brow = wn * 32 + ng * 16 + ((lane & 16) >> 1) + (lane & 7);
                ldm4(bh[2*ng][0], bh[2*ng][1], bh[2*ng+1][0], bh[2*ng+1][1],
                     sBh + SWZ8(brow, bchunk));
                ldm4(bl[2*ng][0], bl[2*ng][1], bl[2*ng+1][0], bl[2*ng+1][1],
                     sBl + SWZ8(brow, bchunk));
            }
#pragma unroll
            for (int mi = 0; mi < 4; mi++)
#pragma unroll
                for (int nf = 0; nf < 4; nf++)
                    mma16816h(acc[mi][nf], af[mi], bh[nf]);
#pragma unroll
            for (int mi = 0; mi < 4; mi++)
#pragma unroll
                for (int nf = 0; nf < 4; nf++)
                    mma16816h(acc[mi][nf], af[mi], bl[nf]);
        }
        __syncthreads();
    }
    const int gid = lane >> 2, tig = lane & 3;
#pragma unroll
    for (int mi = 0; mi < 4; mi++)
#pragma unroll
        for (int nf = 0; nf < 4; nf++) {
            int col = bn + wn * 32 + nf * 8 + tig * 2;
            float b0v = bias[col], b1v = bias[col + 1];
            int r0 = bm + wm * 64 + mi * 16 + gid;
            *(float2*)(C + (size_t)r0 * N + col) =
                make_float2(acc[mi][nf][0] + b0v, acc[mi][nf][1] + b1v);
            *(float2*)(C + (size_t)(r0 + 8) * N + col) =
                make_float2(acc[mi][nf][2] + b0v, acc[mi][nf][3] + b1v);
        }
}

// ---------------- prep kernels (x convert; weight fp16 hi/lo splits) --------
#define XITEMS 3276800
__global__ void prep_x(const float* __restrict__ x, __half* __restrict__ xh) {
    size_t idx = (size_t)blockIdx.x * 256 + threadIdx.x;
    if (idx >= XITEMS) return;
    size_t i = idx * 4;
    float4 v = *(const float4*)(x + i);
    *(uint2*)(xh + i) = make_uint2(packh2(v.x, v.y), packh2(v.z, v.w));
}
__global__ void prep_w(
        const float* __restrict__ Wqks, const float* __restrict__ Wos,
        const float* __restrict__ Wffs, const float* __restrict__ Wqkt,
        const float* __restrict__ Wot,  const float* __restrict__ Wfft,
        const float* __restrict__ Wcnv,
        __half* __restrict__ wh, __half* __restrict__ wl,
        int jbase, int jcount) {
    int li = blockIdx.x * 256 + threadIdx.x;
    if (li >= jcount) return;
    long j = (long)jbase + li;
    const float* W; int K, N, off; int isconv = 0;
    if (j < 98304)                    { W = Wqks; K = 256;  N = 384; off = OFF_QKS; }
    else if ((j -= 98304)  < 196608)  { W = Wos;  K = 768;  N = 256; off = OFF_WOS; }
    else if ((j -= 196608) < 65536)   { W = Wffs; K = 256;  N = 256; off = OFF_FFS; }
    else if ((j -= 65536)  < 131072)  { W = Wqkt; K = 256;  N = 512; off = OFF_QKT; }
    else if ((j -= 131072) < 262144)  { W = Wot;  K = 1024; N = 256; off = OFF_WOT; }
    else if ((j -= 262144) < 65536)   { W = Wfft; K = 256;  N = 256; off = OFF_FFT; }
    else if ((j -= 65536)  < 458752)  { W = Wcnv; K = 1792; N = 256; off = OFF_CNV; isconv = 1; }
    else return;
    float v = W[j];
    __half h = __float2half(v);
    size_t dst;
    if (isconv) {
        int o = (int)(j / 1792), r = (int)(j % 1792);
        int ii = r / 7, kw = r % 7;
        dst = (size_t)off + (size_t)o * 1792 + kw * 256 + ii;
    } else {
        int k = (int)(j / N), n = (int)(j % N);
        dst = (size_t)off + (size_t)n * K + k;
    }
    wh[dst] = h;
    wl[dst] = __float2half(v - __half2float(h));
}

// ------ deint_s: smem-staged, coalesced writes. block per (n,u,t-half) ------
#define DS_SMEM (6 * 2049 * 4)
__global__ __launch_bounds__(256) void deint_s2(const float* __restrict__ qk,
                                                float* __restrict__ qT,
                                                float* __restrict__ kT) {
    extern __shared__ float sms[];
    int b = blockIdx.x;
    int th = b & 1;
    int u = (b >> 1) % VV;
    int n = b / (VV * 2);
    int t0 = th << 5;
    const float* src = qk + ((size_t)(n * VV + u) * TT + t0) * 384;
    for (int i = threadIdx.x; i < 32 * 384; i += 256) {
        int tt = i / 384, col = i % 384;
        int ci = col / 6, r = col % 6;
        sms[r * 2049 + tt * 64 + ci] = src[i];
    }
    __syncthreads();
#pragma unroll
    for (int p = 0; p < 6; p++) {
        int s = (p < 3) ? p : p - 3;
        float* dst = ((p < 3) ? qT : kT) +
                     (((size_t)(n * 3 + s) * VV + u) << 12) + (size_t)t0 * 64;
        for (int i = threadIdx.x; i < 2048; i += 256)
            dst[i] = sms[p * 2049 + i];
    }
}

// ------ deint_t: smem-staged, coalesced writes. block per (n,t) --------------
#define DT_SMEM (8 * 1665 * 4)
__global__ __launch_bounds__(256) void deint_t2(const float* __restrict__ qkt,
                                                float* __restrict__ qd,
                                                float* __restrict__ kd) {
    extern __shared__ float smt[];
    int b = blockIdx.x;
    int t = b % TT, n = b / TT;
    const float* src = qkt + ((size_t)(n * TT + t) * VV) * 512;
    for (int i = threadIdx.x; i < 25 * 512; i += 256) {
        int v = i >> 9, col = i & 511;
        int ci = col >> 3, j = col & 7;
        smt[j * 1665 + v * 64 + ci] = src[i];
    }
    __syncthreads();
#pragma unroll
    for (int p = 0; p < 8; p++) {
        int m = p & 3;
        float* dst = ((p < 4) ? qd : kd) + ((size_t)(n * 4 + m) * TT + t) * 1600;
        for (int i = threadIdx.x; i < 1600; i += 256)
            dst[i] = smt[p * 1665 + i];
    }
}

// spatial attention split-K partials
__global__ __launch_bounds__(128) void att_s_part(
        const float* __restrict__ qT, const float* __restrict__ kT,
        float* __restrict__ ps) {
    int ns = blockIdx.x;
    int kc0 = blockIdx.y << 9;
    __shared__ float qs[25][132], ks[25][132];
    const float* qb = qT + ((size_t)ns * VV << 12);
    const float* kb = kT + ((size_t)ns * VV << 12);
    int t = threadIdx.x;
    int u0 = (t / 25) * 5, v = t % 25;
    float acc[5] = {0.f, 0.f, 0.f, 0.f, 0.f};
    for (int kc = kc0; kc < kc0 + 512; kc += 128) {
        for (int i = t; i < 25 * 128; i += 128) {
            int uu = i >> 7, e = i & 127;
            qs[uu][e] = qb[((size_t)uu << 12) + kc + e];
            ks[uu][e] = kb[((size_t)uu << 12) + kc + e];
        }
        __syncthreads();
        if (t < 125) {
#pragma unroll 4
            for (int e = 0; e < 128; e++) {
                float kv = ks[v][e];
                acc[0] = fmaf(qs[u0 + 0][e], kv, acc[0]);
                acc[1] = fmaf(qs[u0 + 1][e], kv, acc[1]);
                acc[2] = fmaf(qs[u0 + 2][e], kv, acc[2]);
                acc[3] = fmaf(qs[u0 + 3][e], kv, acc[3]);
                acc[4] = fmaf(qs[u0 + 4][e], kv, acc[4]);
            }
        }
        __syncthreads();
    }
    if (t < 125) {
#pragma unroll
        for (int i = 0; i < 5; i++)
            atomicAdd(&ps[(size_t)ns * 625 + (u0 + i) * 25 + v], acc[i]);
    }
}

__global__ void att_s_fin(const float* __restrict__ ps, const float* __restrict__ alphas,
                          const float* __restrict__ att0, float* __restrict__ att) {
    int idx = blockIdx.x * 256 + threadIdx.x;
    if (idx >= 96 * 625) return;
    int ns = idx / 625, r = idx % 625;
    int n = ns / 3, s = ns % 3, u = r / 25, v = r % 25;
    att[((size_t)(n * VV + u) * VV + v) * 3 + s] =
        tanhf(ps[idx] * (1.f / 4096.f)) * alphas[s] + att0[((size_t)u * VV + v) * 3 + s];
}

// y_s: block per (n,t); fp16 output
__global__ __launch_bounds__(256) void ys2(const float* __restrict__ x,
                                           const float* __restrict__ att,
                                           __half* __restrict__ yh) {
    __shared__ float xs[25][256];
    __shared__ float as_[25 * 25 * 3];
    int b = blockIdx.x;
    int n = b >> 6, t = b & 63;
    int tid = threadIdx.x;
    for (int i = tid; i < 25 * 256; i += 256) {
        int u = i >> 8, c = i & 255;
        xs[u][c] = x[((size_t)(n * VV + u) * TT + t) * 256 + c];
    }
    for (int i = tid; i < 1875; i += 256) as_[i] = att[(size_t)n * 1875 + i];
    __syncthreads();
    int c = tid;
#pragma unroll 1
    for (int v = 0; v < VV; v++) {
        float a0 = 0.f, a1 = 0.f, a2 = 0.f;
#pragma unroll
        for (int u = 0; u < VV; u++) {
            float xv = xs[u][c];
            a0 = fmaf(xv, as_[(u * VV + v) * 3 + 0], a0);
            a1 = fmaf(xv, as_[(u * VV + v) * 3 + 1], a1);
            a2 = fmaf(xv, as_[(u * VV + v) * 3 + 2], a2);
        }
        size_t base = ((size_t)(n * VV + v) * TT + t) * 768 + c * 3;
        yh[base]     = __float2half(a0);
        yh[base + 1] = __float2half(a1);
        yh[base + 2] = __float2half(a2);
    }
}

// LN + residual + gelu; writes fp16 (+ optional fp32)
__global__ void ln2(const float* __restrict__ h, const float* __restrict__ res,
                    const float* __restrict__ g, const float* __restrict__ b,
                    float* __restrict__ outf, __half* __restrict__ oh,
                    int G, int mode, int wf) {
    int grp = blockIdx.x;
    const float* hp = h + (size_t)grp * G;
    const float* rp = res + (size_t)grp * G;
    float s = 0.f, sq = 0.f;
    for (int i = threadIdx.x; i < G; i += blockDim.x) {
        float v = hp[i]; s += v; sq = fmaf(v, v, sq);
    }
    for (int o = 16; o; o >>= 1) {
        s += __shfl_down_sync(0xffffffffu, s, o);
        sq += __shfl_down_sync(0xffffffffu, sq, o);
    }
    __shared__ float ss[8], sqs[8];
    __shared__ float mean_s, inv_s;
    int w = threadIdx.x >> 5;
    if ((threadIdx.x & 31) == 0) { ss[w] = s; sqs[w] = sq; }
    __syncthreads();
    if (threadIdx.x == 0) {
        float S = 0.f, Q = 0.f;
        for (int i = 0; i < 8; i++) { S += ss[i]; Q += sqs[i]; }
        float mean = S / G;
        float var = Q / G - mean * mean;
        mean_s = mean; inv_s = rsqrtf(var + 1e-5f);
    }
    __syncthreads();
    float mean = mean_s, inv = inv_s;
    int n = 0, v = 0;
    if (mode == 1) { n = grp / VV; v = grp % VV; }
    for (int i = threadIdx.x; i < G; i += blockDim.x) {
        float val = gelu_f(rp[i] + fmaf((hp[i] - mean) * inv, g[i], b[i]));
        size_t dst;
        if (mode == 0) dst = (size_t)grp * G + i;
        else {
            int t = i >> 8, c = i & 255;
            dst = ((size_t)(n * TT + t) * VV + v) * 256 + c;
        }
        if (wf) outf[dst] = val;
        oh[dst] = __float2half(val);
    }
}

// temporal attention split-K partials
__global__ __launch_bounds__(256) void att_t_part(
        const float* __restrict__ qd, const float* __restrict__ kd,
        float* __restrict__ pt) {
    int nm = blockIdx.x;
    int kb = blockIdx.y * 320;
    __shared__ float Qs[64][68], Ks[64][68];
    const float* qb = qd + (size_t)nm * TT * 1600;
    const float* kb_ = kd + (size_t)nm * TT * 1600;
    const int tid = threadIdx.x;
    const int tx = tid & 15, ty = tid >> 4;
    const int lr = tid >> 2, lc = (tid & 3) << 4;
    float acc[4][4] = {};
    for (int kc = kb; kc < kb + 320; kc += 64) {
#pragma unroll
        for (int j = 0; j < 4; j++) {
            float4 q4 = *(const float4*)(qb + (size_t)lr * 1600 + kc + lc + j * 4);
            float4 k4 = *(const float4*)(kb_ + (size_t)lr * 1600 + kc + lc + j * 4);
            Qs[lc + j*4 + 0][lr] = q4.x; Qs[lc + j*4 + 1][lr] = q4.y;
            Qs[lc + j*4 + 2][lr] = q4.z; Qs[lc + j*4 + 3][lr] = q4.w;
            Ks[lc + j*4 + 0][lr] = k4.x; Ks[lc + j*4 + 1][lr] = k4.y;
            Ks[lc + j*4 + 2][lr] = k4.z; Ks[lc + j*4 + 3][lr] = k4.w;
        }
        __syncthreads();
#pragma unroll 8
        for (int kk = 0; kk < 64; kk++) {
            float4 aq = *(const float4*)(&Qs[kk][ty << 2]);
            float4 bk = *(const float4*)(&Ks[kk][tx << 2]);
            float a[4] = {aq.x, aq.y, aq.z, aq.w};
            float b[4] = {bk.x, bk.y, bk.z, bk.w};
#pragma unroll
            for (int i = 0; i < 4; i++)
#pragma unroll
                for (int j = 0; j < 4; j++) acc[i][j] = fmaf(a[i], b[j], acc[i][j]);
        }
        __syncthreads();
    }
#pragma unroll
    for (int i = 0; i < 4; i++)
#pragma unroll
        for (int j = 0; j < 4; j++) {
            int t_ = (ty << 2) + i, q_ = (tx << 2) + j;
            atomicAdd(&pt[(size_t)nm * 4096 + t_ * 64 + q_], acc[i][j]);
        }
}

__global__ void att_t_fin(const float* __restrict__ pt, const float* __restrict__ alf,
                          const float* __restrict__ alb, float* __restrict__ attf,
                          float* __restrict__ attb) {
    int idx = blockIdx.x * 256 + threadIdx.x;
    if (idx >= 128 * 4096) return;
    int nm = idx >> 12, r = idx & 4095;
    int t = r >> 6, q = r & 63;
    int n = nm >> 2, m = nm & 3, s = m & 1, dir = m >> 1;
    float val = tanhf(pt[idx] * (1.f / 1600.f)) * (dir ? alb[s] : alf[s]);
    size_t o = ((size_t)(n * TT + q) * TT + t) * 2 + s;
    if (dir == 0) attf[o] = (q <= t) ? val : 0.f;
    else          attb[o] = (q >= t) ? val : 0.f;
}

// z apply: fp16 output
__global__ __launch_bounds__(256) void z2k(const float* __restrict__ y2t,
                                           const float* __restrict__ attf,
                                           const float* __restrict__ attb,
                                           __half* __restrict__ zh) {
    extern __shared__ float zs[];
    float* ys = zs;
    float* as_ = zs + 64 * 256;
    int b = blockIdx.x;
    int n = b / VV, v = b % VV;
    int tid = threadIdx.x;
    for (int i = tid; i < 64 * 256; i += 256) {
        int t = i >> 8, c = i & 255;
        ys[t * 256 + c] = y2t[((size_t)(n * TT + t) * VV + v) * 256 + c];
    }
    __syncthreads();
    int c = tid;
    for (int q = 0; q < TT; q++) {
        if (tid < 128) as_[tid] = attf[(size_t)n * 8192 + q * 128 + tid];
        else           as_[tid] = attb[(size_t)n * 8192 + q * 128 + (tid - 128)];
        __syncthreads();
        float f0 = 0.f, f1 = 0.f, b0 = 0.f, b1 = 0.f;
#pragma unroll 8
        for (int t = 0; t < TT; t++) {
            float yv = ys[t * 256 + c];
            f0 = fmaf(yv, as_[t * 2], f0);       f1 = fmaf(yv, as_[t * 2 + 1], f1);
            b0 = fmaf(yv, as_[128 + t * 2], b0); b1 = fmaf(yv, as_[128 + t * 2 + 1], b1);
        }
        size_t base = ((size_t)(n * TT + q) * VV + v) * 1024;
        *(uint32_t*)(zh + base + c * 2) = packh2(f0, f1);
        *(uint32_t*)(zh + base + 512 + c * 2) = packh2(b0, b1);
        __syncthreads();
    }
}

__global__ void final_kernel(const float* __restrict__ z2, const float* __restrict__ cv,
                             const float* __restrict__ bn_g, const float* __restrict__ bn_b,
                             const float* __restrict__ bn_m, const float* __restrict__ bn_v,
                             float* __restrict__ out) {
    size_t i = (size_t)blockIdx.x * 256 + threadIdx.x;
    int o = (int)(i & 255);
    size_t r = i >> 8;
    int v = (int)(r % VV);
    size_t r2 = r / VV;
    int t = (int)(r2 % TT);
    int n = (int)(r2 / TT);
    float c1 = fmaf((cv[i] - bn_m[o]) * rsqrtf(bn_v[o] + 1e-5f), bn_g[o], bn_b[o]);
    out[((size_t)(n * VV + v) * TT + t) * 256 + o] = gelu_f(z2[i] + c1);
}

// ------------------------------- launcher -----------------------------------
extern "C" void kernel_launch(void* const* d_in, const int* in_sizes, int n_in,
                              void* d_out, int out_size) {
    const float* x       = (const float*)d_in[0];
    const float* Wqk_s   = (const float*)d_in[1];
    const float* bqk_s   = (const float*)d_in[2];
    const float* alphas  = (const float*)d_in[3];
    const float* att0s   = (const float*)d_in[4];
    const float* Wo_s    = (const float*)d_in[5];
    const float* bo_s    = (const float*)d_in[6];
    const float* g_os    = (const float*)d_in[7];
    const float* b_os    = (const float*)d_in[8];
    const float* Wff_s   = (const float*)d_in[9];
    const float* bff_s   = (const float*)d_in[10];
    const float* g_ffs   = (const float*)d_in[11];
    const float* b_ffs   = (const float*)d_in[12];
    const float* Wqk_t   = (const float*)d_in[13];
    const float* bqk_t   = (const float*)d_in[14];
    const float* alphat_f= (const float*)d_in[15];
    const float* alphat_b= (const float*)d_in[16];
    const float* Wo_t    = (const float*)d_in[17];
    const float* bo_t    = (const float*)d_in[18];
    const float* g_ot    = (const float*)d_in[19];
    const float* b_ot    = (const float*)d_in[20];
    const float* Wff_t   = (const float*)d_in[21];
    const float* bff_t   = (const float*)d_in[22];
    const float* g_fft   = (const float*)d_in[23];
    const float* b_fft   = (const float*)d_in[24];
    const float* conv_w  = (const float*)d_in[25];
    const float* conv_b  = (const float*)d_in[26];
    const float* bn_g    = (const float*)d_in[27];
    const float* bn_b    = (const float*)d_in[28];
    const float* bn_m    = (const float*)d_in[29];
    const float* bn_v    = (const float*)d_in[30];
    float* out = (float*)d_out;

    void *pB, *pH, *pY1, *pY2, *pZ2, *pAS, *pAF, *pAB, *pWH, *pWL, *pPS, *pPT;
    void *pAH, *pXH, *pY1H, *pY2H, *pZ2H;
    cudaGetSymbolAddress(&pB,  g_bufB);
    cudaGetSymbolAddress(&pH,  g_h);
    cudaGetSymbolAddress(&pY1, g_y1);
    cudaGetSymbolAddress(&pY2, g_y2);
    cudaGetSymbolAddress(&pZ2, g_z2);
    cudaGetSymbolAddress(&pAS, g_atts);
    cudaGetSymbolAddress(&pAF, g_attf);
    cudaGetSymbolAddress(&pAB, g_attb);
    cudaGetSymbolAddress(&pPS, g_ps);
    cudaGetSymbolAddress(&pPT, g_pt);
    cudaGetSymbolAddress(&pWH, g_wh);
    cudaGetSymbolAddress(&pWL, g_wl);
    cudaGetSymbolAddress(&pAH, g_ah);
    cudaGetSymbolAddress(&pXH, g_xh);
    cudaGetSymbolAddress(&pY1H, g_y1h);
    cudaGetSymbolAddress(&pY2H, g_y2h);
    cudaGetSymbolAddress(&pZ2H, g_z2h);
    float* bufB = (float*)pB;
    float* h    = (float*)pH;  float* y1   = (float*)pY1;
    float* y2   = (float*)pY2; float* z2b  = (float*)pZ2;
    float* atts = (float*)pAS; float* attf = (float*)pAF;
    float* attb = (float*)pAB;
    float* ps   = (float*)pPS; float* pt   = (float*)pPT;
    __half* wh  = (__half*)pWH;
    __half* wl  = (__half*)pWL;
    __half* ah  = (__half*)pAH;
    __half* xh  = (__half*)pXH;
    __half* y1h = (__half*)pY1H;
    __half* y2h = (__half*)pY2H;
    __half* z2h = (__half*)pZ2H;

    cudaFuncSetAttribute(gemm_h, cudaFuncAttributeMaxDynamicSharedMemorySize, GSM);
    cudaFuncSetAttribute(conv_h, cudaFuncAttributeMaxDynamicSharedMemorySize, GSM);
    cudaFuncSetAttribute(z2k, cudaFuncAttributeMaxDynamicSharedMemorySize, (64*256 + 256) * 4);
    cudaFuncSetAttribute(deint_s2, cudaFuncAttributeMaxDynamicSharedMemorySize, DS_SMEM);
    cudaFuncSetAttribute(deint_t2, cudaFuncAttributeMaxDynamicSharedMemorySize, DT_SMEM);

    dim3 blk(256);
    const int MB = RTOT / 128;   // 400
    const int WHALF = WTOT / 2;

    prep_x<<<(XITEMS + 255) / 256, blk>>>(x, xh);
    prep_w<<<(WHALF + 255) / 256, blk>>>(Wqk_s, Wo_s, Wff_s, Wqk_t, Wo_t, Wff_t,
                                         conv_w, wh, wl, 0, WHALF);
    prep_w<<<(WHALF + 255) / 256, blk>>>(Wqk_s, Wo_s, Wff_s, Wqk_t, Wo_t, Wff_t,
                                         conv_w, wh, wl, WHALF, WTOT - WHALF);
    cudaMemsetAsync(ps, 0, 96 * 625 * sizeof(float));
    cudaMemsetAsync(pt, 0, 128 * 4096 * sizeof(float));

    // Stage 1: spatial
    gemm_h<<<dim3(3, MB), blk, GSM>>>(xh, wh + OFF_QKS, wl + OFF_QKS, bqk_s, bufB, RTOT, 384, 256);
    deint_s2<<<NN * VV * 2, blk, DS_SMEM>>>(bufB, h, y1);
    att_s_part<<<dim3(96, 8), 128>>>(h, y1, ps);
    att_s_fin<<<(96 * 625 + 255) / 256, blk>>>(ps, alphas, att0s, atts);
    ys2<<<NN * TT, blk>>>(x, atts, ah);
    gemm_h<<<dim3(2, MB), blk, GSM>>>(ah, wh + OFF_WOS, wl + OFF_WOS, bo_s, h, RTOT, 256, 768);
    ln2<<<NN*VV, blk>>>(h, x, g_os, b_os, y1, y1h, TT*256, 0, 0);
    gemm_h<<<dim3(2, MB), blk, GSM>>>(y1h, wh + OFF_FFS, wl + OFF_FFS, bff_s, h, RTOT, 256, 256);
    ln2<<<NN*VV, blk>>>(h, x, g_ffs, b_ffs, y2, y2h, TT*256, 1, 1);

    // Stage 2: temporal
    gemm_h<<<dim3(4, MB), blk, GSM>>>(y2h, wh + OFF_QKT, wl + OFF_QKT, bqk_t, bufB, RTOT, 512, 256);
    deint_t2<<<NN * TT, blk, DT_SMEM>>>(bufB, h, y1);
    att_t_part<<<dim3(128, 5), blk>>>(h, y1, pt);
    att_t_fin<<<(128 * 4096 + 255) / 256, blk>>>(pt, alphat_f, alphat_b, attf, attb);
    z2k<<<NN * VV, blk, (64*256 + 256) * 4>>>(y2, attf, attb, ah);
    gemm_h<<<dim3(2, MB), blk, GSM>>>(ah, wh + OFF_WOT, wl + OFF_WOT, bo_t, h, RTOT, 256, 1024);
    ln2<<<NN*TT, blk>>>(h, y2, g_ot, b_ot, y1, y1h, VV*256, 0, 0);
    gemm_h<<<dim3(2, MB), blk, GSM>>>(y1h, wh + OFF_FFT, wl + OFF_FFT, bff_t, h, RTOT, 256, 256);
    ln2<<<NN*TT, blk>>>(h, y2, g_fft, b_fft, z2b, z2h, VV*256, 0, 1);

    // Stage 3: conv + BN + gelu + transpose
    conv_h<<<dim3(2, MB), blk, GSM>>>(z2h, wh + OFF_CNV, wl + OFF_CNV, conv_b, h);
    final_kernel<<<RTOT, blk>>>(z2b, h, bn_g, bn_b, bn_m, bn_v, out);
}

// round 15
// speedup vs baseline: 1.1912x; 1.1912x over previous
#include <cuda_runtime.h>
#include <cuda_fp16.h>
#include <math.h>
#include <stdint.h>

#define NN 32
#define VV 25
#define TT 64
#define RTOT (NN*VV*TT)   /* 51200 */

// ------------------------- scratch (device globals) -------------------------
__device__ float g_bufB[(size_t)RTOT * 512];
__device__ float g_h   [(size_t)RTOT * 256];
__device__ float g_y1  [(size_t)RTOT * 256];
__device__ float g_y2  [(size_t)RTOT * 256];
__device__ float g_z2  [(size_t)RTOT * 256];
__device__ float g_atts[NN*VV*VV*3];
__device__ float g_attf[NN*TT*TT*2];   // transposed layout [n][q][t][s]
__device__ float g_attb[NN*TT*TT*2];
__device__ float g_ps  [96*625];
__device__ float g_pt  [128*64*64];
// fp16 activation buffers (16B-aligned for cp.async)
__device__ __align__(128) __half g_ah [(size_t)RTOT * 1024];
__device__ __align__(128) __half g_xh [(size_t)RTOT * 256];
__device__ __align__(128) __half g_y1h[(size_t)RTOT * 256];
__device__ __align__(128) __half g_y2h[(size_t)RTOT * 256];
__device__ __align__(128) __half g_z2h[(size_t)RTOT * 256];
#define WTOT 1277952
__device__ __align__(128) __half g_wh[WTOT];
#define OFF_QKS 0         /* K=256  N=384  */
#define OFF_WOS 98304     /* K=768  N=256  */
#define OFF_FFS 294912    /* K=256  N=256  */
#define OFF_QKT 360448    /* K=256  N=512  */
#define OFF_WOT 491520    /* K=1024 N=256  */
#define OFF_FFT 753664    /* K=256  N=256  */
#define OFF_CNV 819200    /* K=1792 N=256  */

__device__ __forceinline__ float gelu_f(float x) {
    return 0.5f * x * (1.0f + erff(x * 0.7071067811865475f));
}
__device__ __forceinline__ uint32_t packh2(float a, float b) {
    __half2 h = __floats2half2_rn(a, b);
    return *(uint32_t*)&h;
}
__device__ __forceinline__ uint32_t smem_u32(const void* p) {
    uint32_t a;
    asm("{ .reg .u64 t; cvta.to.shared.u64 t, %1; cvt.u32.u64 %0, t; }" : "=r"(a) : "l"(p));
    return a;
}
__device__ __forceinline__ void ldm4(uint32_t &r0, uint32_t &r1, uint32_t &r2,
                                     uint32_t &r3, uint32_t a) {
    asm volatile("ldmatrix.sync.aligned.m8n8.x4.shared.b16 {%0,%1,%2,%3}, [%4];"
        : "=r"(r0), "=r"(r1), "=r"(r2), "=r"(r3) : "r"(a));
}
__device__ __forceinline__ void mma16816h(float* c, const uint32_t* a, const uint32_t* b) {
    asm volatile(
        "mma.sync.aligned.m16n8k16.row.col.f32.f16.f16.f32 "
        "{%0,%1,%2,%3}, {%4,%5,%6,%7}, {%8,%9}, {%0,%1,%2,%3};"
        : "+f"(c[0]), "+f"(c[1]), "+f"(c[2]), "+f"(c[3])
        : "r"(a[0]), "r"(a[1]), "r"(a[2]), "r"(a[3]), "r"(b[0]), "r"(b[1]));
}
__device__ __forceinline__ void cpa16(uint32_t dst, const void* src) {
    asm volatile("cp.async.cg.shared.global [%0], [%1], 16;" :: "r"(dst), "l"(src));
}
__device__ __forceinline__ void cpa16z(uint32_t dst, const void* src, int sz) {
    asm volatile("cp.async.cg.shared.global [%0], [%1], 16, %2;" :: "r"(dst), "l"(src), "r"(sz));
}
#define CPA_COMMIT() asm volatile("cp.async.commit_group;" ::: "memory")
#define CPA_WAIT1() asm volatile("cp.async.wait_group 1;" ::: "memory")
#define CPA_WAIT0() asm volatile("cp.async.wait_group 0;" ::: "memory")

// smem swizzle for 128B rows (64 fp16): 16B chunk ch of row r at (ch ^ (r&7))*16
#define SWZ8(row, ch) ((uint32_t)((row) * 128 + (((ch) ^ ((row) & 7)) << 4)))

// == fp16 HMMA GEMM (single-term): 128x128 tile, warp 64x32, k-chunk 64 ======
// C[M,N] = A[M,K](fp16) @ B[K,N](fp16) + bias; B stored [N][K].
// stage 32KB: A(16K) B(16K); 2 stages = 64KB, 2 CTA/SM. Prefetch distance 1.
#define GSM (2*32768)
__global__ __launch_bounds__(256, 2) void gemm_h(
        const __half* __restrict__ A, const __half* __restrict__ B,
        const float* __restrict__ bias, float* __restrict__ C,
        int M, int N, int K) {
    extern __shared__ char sm[];
    const uint32_t sbase = smem_u32(sm);
    const int tid = threadIdx.x, lane = tid & 31, w = tid >> 5;
    const int wm = w & 1, wn = w >> 1;     // warp tile: 64 rows x 32 cols
    const int bm = blockIdx.y << 7, bn = blockIdx.x << 7;
    float acc[4][4][4];
#pragma unroll
    for (int i = 0; i < 4; i++)
#pragma unroll
        for (int j = 0; j < 4; j++)
#pragma unroll
            for (int q = 0; q < 4; q++) acc[i][j][q] = 0.f;
    const int nch = K >> 6;

    auto load_stage = [&](int c) {
        uint32_t st = sbase + (c & 1) * 32768;
        const int k0 = c << 6;
#pragma unroll
        for (int j = 0; j < 4; j++) {
            int f = j * 256 + tid;
            int row = f >> 3, ch = f & 7;
            uint32_t off = SWZ8(row, ch);
            cpa16(st + off,         A + (size_t)(bm + row) * K + k0 + ch * 8);
            cpa16(st + 16384 + off, B + (size_t)(bn + row) * K + k0 + ch * 8);
        }
        CPA_COMMIT();
    };
    load_stage(0);
    for (int c = 0; c < nch; c++) {
        if (c + 1 < nch) { load_stage(c + 1); CPA_WAIT1(); }
        else CPA_WAIT0();
        __syncthreads();
        const uint32_t sA = sbase + (c & 1) * 32768;
        const uint32_t sB = sA + 16384;
#pragma unroll
        for (int kk = 0; kk < 4; kk++) {
            uint32_t af[4][4];
            const int arow = wm * 64 + (lane & 15);
            const int achunk = kk * 2 + (lane >> 4);
#pragma unroll
            for (int mi = 0; mi < 4; mi++) {
                int row = arow + mi * 16;
                ldm4(af[mi][0], af[mi][1], af[mi][2], af[mi][3], sA + SWZ8(row, achunk));
            }
            const int bchunk = kk * 2 + ((lane >> 3) & 1);
            uint32_t bf[4][2];
#pragma unroll
            for (int ng = 0; ng < 2; ng++) {
                int brow = wn * 32 + ng * 16 + ((lane & 16) >> 1) + (lane & 7);
                ldm4(bf[2*ng][0], bf[2*ng][1], bf[2*ng+1][0], bf[2*ng+1][1],
                     sB + SWZ8(brow, bchunk));
            }
#pragma unroll
            for (int mi = 0; mi < 4; mi++)
#pragma unroll
                for (int nf = 0; nf < 4; nf++)
                    mma16816h(acc[mi][nf], af[mi], bf[nf]);
        }
        __syncthreads();
    }
    const int gid = lane >> 2, tig = lane & 3;
#pragma unroll
    for (int mi = 0; mi < 4; mi++)
#pragma unroll
        for (int nf = 0; nf < 4; nf++) {
            int col = bn + wn * 32 + nf * 8 + tig * 2;
            float b0v = bias[col], b1v = bias[col + 1];
            int r0 = bm + wm * 64 + mi * 16 + gid;
            *(float2*)(C + (size_t)r0 * N + col) =
                make_float2(acc[mi][nf][0] + b0v, acc[mi][nf][1] + b1v);
            *(float2*)(C + (size_t)(r0 + 8) * N + col) =
                make_float2(acc[mi][nf][2] + b0v, acc[mi][nf][3] + b1v);
        }
}

// == conv (implicit im2col) single-term fp16 HMMA: K=1792, warp 64x32 ========
__global__ __launch_bounds__(256, 2) void conv_h(
        const __half* __restrict__ Z, const __half* __restrict__ B,
        const float* __restrict__ bias, float* __restrict__ C) {
    const int N = 256, K = 1792;
    extern __shared__ char sm[];
    const uint32_t sbase = smem_u32(sm);
    const int tid = threadIdx.x, lane = tid & 31, w = tid >> 5;
    const int wm = w & 1, wn = w >> 1;
    const int bm = blockIdx.y << 7, bn = blockIdx.x << 7;
    float acc[4][4][4];
#pragma unroll
    for (int i = 0; i < 4; i++)
#pragma unroll
        for (int j = 0; j < 4; j++)
#pragma unroll
            for (int q = 0; q < 4; q++) acc[i][j][q] = 0.f;
    const int nch = K >> 6;   // 28

    auto load_stage = [&](int c) {
        uint32_t st = sbase + (c & 1) * 32768;
        const int k0 = c << 6;
        const int dt = (k0 >> 8) - 3;
        const int iio = k0 & 255;
#pragma unroll
        for (int j = 0; j < 4; j++) {
            int f = j * 256 + tid;
            int row = f >> 3, ch = f & 7;
            uint32_t off = SWZ8(row, ch);
            int grow = bm + row;
            int t = (grow / VV) % TT;
            int tt = t + dt;
            int ok = (tt >= 0 && tt < TT);
            size_t srcoff = ok ? ((size_t)grow + (size_t)dt * VV) * 256 + iio + ch * 8 : 0;
            cpa16z(st + off, Z + srcoff, ok ? 16 : 0);
            cpa16(st + 16384 + off, B + (size_t)(bn + row) * K + k0 + ch * 8);
        }
        CPA_COMMIT();
    };
    load_stage(0);
    for (int c = 0; c < nch; c++) {
        if (c + 1 < nch) { load_stage(c + 1); CPA_WAIT1(); }
        else CPA_WAIT0();
        __syncthreads();
        const uint32_t sA = sbase + (c & 1) * 32768;
        const uint32_t sB = sA + 16384;
#pragma unroll
        for (int kk = 0; kk < 4; kk++) {
            uint32_t af[4][4];
            const int arow = wm * 64 + (lane & 15);
            const int achunk = kk * 2 + (lane >> 4);
#pragma unroll
            for (int mi = 0; mi < 4; mi++) {
                int row = arow + mi * 16;
                ldm4(af[mi][0], af[mi][1], af[mi][2], af[mi][3], sA + SWZ8(row, achunk));
            }
            const int bchunk = kk * 2 + ((lane >> 3) & 1);
            uint32_t bf[4][2];
#pragma unroll
            for (int ng = 0; ng < 2; ng++) {
                int brow = wn * 32 + ng * 16 + ((lane & 16) >> 1) + (lane & 7);
                ldm4(bf[2*ng][0], bf[2*ng][1], bf[2*ng+1][0], bf[2*ng+1][1],
                     sB + SWZ8(brow, bchunk));
            }
#pragma unroll
            for (int mi = 0; mi < 4; mi++)
#pragma unroll
                for (int nf = 0; nf < 4; nf++)
                    mma16816h(acc[mi][nf], af[mi], bf[nf]);
        }
        __syncthreads();
    }
    const int gid = lane >> 2, tig = lane & 3;
#pragma unroll
    for (int mi = 0; mi < 4; mi++)
#pragma unroll
        for (int nf = 0; nf < 4; nf++) {
            int col = bn + wn * 32 + nf * 8 + tig * 2;
            float b0v = bias[col], b1v = bias[col + 1];
            int r0 = bm + wm * 64 + mi * 16 + gid;
            *(float2*)(C + (size_t)r0 * N + col) =
                make_float2(acc[mi][nf][0] + b0v, acc[mi][nf][1] + b1v);
            *(float2*)(C + (size_t)(r0 + 8) * N + col) =
                make_float2(acc[mi][nf][2] + b0v, acc[mi][nf][3] + b1v);
        }
}

// ---------------- prep kernels (x convert; weight fp16 transpose) -----------
#define XITEMS 3276800
__global__ void prep_x(const float* __restrict__ x, __half* __restrict__ xh) {
    size_t idx = (size_t)blockIdx.x * 256 + threadIdx.x;
    if (idx >= XITEMS) return;
    size_t i = idx * 4;
    float4 v = *(const float4*)(x + i);
    *(uint2*)(xh + i) = make_uint2(packh2(v.x, v.y), packh2(v.z, v.w));
}
__global__ void prep_w(
        const float* __restrict__ Wqks, const float* __restrict__ Wos,
        const float* __restrict__ Wffs, const float* __restrict__ Wqkt,
        const float* __restrict__ Wot,  const float* __restrict__ Wfft,
        const float* __restrict__ Wcnv,
        __half* __restrict__ wh, int jbase, int jcount) {
    int li = blockIdx.x * 256 + threadIdx.x;
    if (li >= jcount) return;
    long j = (long)jbase + li;
    const float* W; int K, N, off; int isconv = 0;
    if (j < 98304)                    { W = Wqks; K = 256;  N = 384; off = OFF_QKS; }
    else if ((j -= 98304)  < 196608)  { W = Wos;  K = 768;  N = 256; off = OFF_WOS; }
    else if ((j -= 196608) < 65536)   { W = Wffs; K = 256;  N = 256; off = OFF_FFS; }
    else if ((j -= 65536)  < 131072)  { W = Wqkt; K = 256;  N = 512; off = OFF_QKT; }
    else if ((j -= 131072) < 262144)  { W = Wot;  K = 1024; N = 256; off = OFF_WOT; }
    else if ((j -= 262144) < 65536)   { W = Wfft; K = 256;  N = 256; off = OFF_FFT; }
    else if ((j -= 65536)  < 458752)  { W = Wcnv; K = 1792; N = 256; off = OFF_CNV; isconv = 1; }
    else return;
    float v = W[j];
    size_t dst;
    if (isconv) {
        int o = (int)(j / 1792), r = (int)(j % 1792);
        int ii = r / 7, kw = r % 7;
        dst = (size_t)off + (size_t)o * 1792 + kw * 256 + ii;
    } else {
        int k = (int)(j / N), n = (int)(j % N);
        dst = (size_t)off + (size_t)n * K + k;
    }
    wh[dst] = __float2half(v);
}

// ------ deint_s: smem-staged, coalesced writes. block per (n,u,t-half) ------
#define DS_SMEM (6 * 2049 * 4)
__global__ __launch_bounds__(256) void deint_s2(const float* __restrict__ qk,
                                                float* __restrict__ qT,
                                                float* __restrict__ kT) {
    extern __shared__ float sms[];
    int b = blockIdx.x;
    int th = b & 1;
    int u = (b >> 1) % VV;
    int n = b / (VV * 2);
    int t0 = th << 5;
    const float* src = qk + ((size_t)(n * VV + u) * TT + t0) * 384;
    for (int i = threadIdx.x; i < 32 * 384; i += 256) {
        int tt = i / 384, col = i % 384;
        int ci = col / 6, r = col % 6;
        sms[r * 2049 + tt * 64 + ci] = src[i];
    }
    __syncthreads();
#pragma unroll
    for (int p = 0; p < 6; p++) {
        int s = (p < 3) ? p : p - 3;
        float* dst = ((p < 3) ? qT : kT) +
                     (((size_t)(n * 3 + s) * VV + u) << 12) + (size_t)t0 * 64;
        for (int i = threadIdx.x; i < 2048; i += 256)
            dst[i] = sms[p * 2049 + i];
    }
}

// ------ deint_t: smem-staged, coalesced writes. block per (n,t) --------------
#define DT_SMEM (8 * 1665 * 4)
__global__ __launch_bounds__(256) void deint_t2(const float* __restrict__ qkt,
                                                float* __restrict__ qd,
                                                float* __restrict__ kd) {
    extern __shared__ float smt[];
    int b = blockIdx.x;
    int t = b % TT, n = b / TT;
    const float* src = qkt + ((size_t)(n * TT + t) * VV) * 512;
    for (int i = threadIdx.x; i < 25 * 512; i += 256) {
        int v = i >> 9, col = i & 511;
        int ci = col >> 3, j = col & 7;
        smt[j * 1665 + v * 64 + ci] = src[i];
    }
    __syncthreads();
#pragma unroll
    for (int p = 0; p < 8; p++) {
        int m = p & 3;
        float* dst = ((p < 4) ? qd : kd) + ((size_t)(n * 4 + m) * TT + t) * 1600;
        for (int i = threadIdx.x; i < 1600; i += 256)
            dst[i] = smt[p * 1665 + i];
    }
}

// spatial attention split-K partials
__global__ __launch_bounds__(128) void att_s_part(
        const float* __restrict__ qT, const float* __restrict__ kT,
        float* __restrict__ ps) {
    int ns = blockIdx.x;
    int kc0 = blockIdx.y << 9;
    __shared__ float qs[25][132], ks[25][132];
    const float* qb = qT + ((size_t)ns * VV << 12);
    const float* kb = kT + ((size_t)ns * VV << 12);
    int t = threadIdx.x;
    int u0 = (t / 25) * 5, v = t % 25;
    float acc[5] = {0.f, 0.f, 0.f, 0.f, 0.f};
    for (int kc = kc0; kc < kc0 + 512; kc += 128) {
        for (int i = t; i < 25 * 128; i += 128) {
            int uu = i >> 7, e = i & 127;
            qs[uu][e] = qb[((size_t)uu << 12) + kc + e];
            ks[uu][e] = kb[((size_t)uu << 12) + kc + e];
        }
        __syncthreads();
        if (t < 125) {
#pragma unroll 4
            for (int e = 0; e < 128; e++) {
                float kv = ks[v][e];
                acc[0] = fmaf(qs[u0 + 0][e], kv, acc[0]);
                acc[1] = fmaf(qs[u0 + 1][e], kv, acc[1]);
                acc[2] = fmaf(qs[u0 + 2][e], kv, acc[2]);
                acc[3] = fmaf(qs[u0 + 3][e], kv, acc[3]);
                acc[4] = fmaf(qs[u0 + 4][e], kv, acc[4]);
            }
        }
        __syncthreads();
    }
    if (t < 125) {
#pragma unroll
        for (int i = 0; i < 5; i++)
            atomicAdd(&ps[(size_t)ns * 625 + (u0 + i) * 25 + v], acc[i]);
    }
}

__global__ void att_s_fin(const float* __restrict__ ps, const float* __restrict__ alphas,
                          const float* __restrict__ att0, float* __restrict__ att) {
    int idx = blockIdx.x * 256 + threadIdx.x;
    if (idx >= 96 * 625) return;
    int ns = idx / 625, r = idx % 625;
    int n = ns / 3, s = ns % 3, u = r / 25, v = r % 25;
    att[((size_t)(n * VV + u) * VV + v) * 3 + s] =
        tanhf(ps[idx] * (1.f / 4096.f)) * alphas[s] + att0[((size_t)u * VV + v) * 3 + s];
}

// y_s: block per (n,t); fp16 output
__global__ __launch_bounds__(256) void ys2(const float* __restrict__ x,
                                           const float* __restrict__ att,
                                           __half* __restrict__ yh) {
    __shared__ float xs[25][256];
    __shared__ float as_[25 * 25 * 3];
    int b = blockIdx.x;
    int n = b >> 6, t = b & 63;
    int tid = threadIdx.x;
    for (int i = tid; i < 25 * 256; i += 256) {
        int u = i >> 8, c = i & 255;
        xs[u][c] = x[((size_t)(n * VV + u) * TT + t) * 256 + c];
    }
    for (int i = tid; i < 1875; i += 256) as_[i] = att[(size_t)n * 1875 + i];
    __syncthreads();
    int c = tid;
#pragma unroll 1
    for (int v = 0; v < VV; v++) {
        float a0 = 0.f, a1 = 0.f, a2 = 0.f;
#pragma unroll
        for (int u = 0; u < VV; u++) {
            float xv = xs[u][c];
            a0 = fmaf(xv, as_[(u * VV + v) * 3 + 0], a0);
            a1 = fmaf(xv, as_[(u * VV + v) * 3 + 1], a1);
            a2 = fmaf(xv, as_[(u * VV + v) * 3 + 2], a2);
        }
        size_t base = ((size_t)(n * VV + v) * TT + t) * 768 + c * 3;
        yh[base]     = __float2half(a0);
        yh[base + 1] = __float2half(a1);
        yh[base + 2] = __float2half(a2);
    }
}

// LN + residual + gelu; writes fp16 (+ optional fp32)
__global__ void ln2(const float* __restrict__ h, const float* __restrict__ res,
                    const float* __restrict__ g, const float* __restrict__ b,
                    float* __restrict__ outf, __half* __restrict__ oh,
                    int G, int mode, int wf) {
    int grp = blockIdx.x;
    const float* hp = h + (size_t)grp * G;
    const float* rp = res + (size_t)grp * G;
    float s = 0.f, sq = 0.f;
    for (int i = threadIdx.x; i < G; i += blockDim.x) {
        float v = hp[i]; s += v; sq = fmaf(v, v, sq);
    }
    for (int o = 16; o; o >>= 1) {
        s += __shfl_down_sync(0xffffffffu, s, o);
        sq += __shfl_down_sync(0xffffffffu, sq, o);
    }
    __shared__ float ss[8], sqs[8];
    __shared__ float mean_s, inv_s;
    int w = threadIdx.x >> 5;
    if ((threadIdx.x & 31) == 0) { ss[w] = s; sqs[w] = sq; }
    __syncthreads();
    if (threadIdx.x == 0) {
        float S = 0.f, Q = 0.f;
        for (int i = 0; i < 8; i++) { S += ss[i]; Q += sqs[i]; }
        float mean = S / G;
        float var = Q / G - mean * mean;
        mean_s = mean; inv_s = rsqrtf(var + 1e-5f);
    }
    __syncthreads();
    float mean = mean_s, inv = inv_s;
    int n = 0, v = 0;
    if (mode == 1) { n = grp / VV; v = grp % VV; }
    for (int i = threadIdx.x; i < G; i += blockDim.x) {
        float val = gelu_f(rp[i] + fmaf((hp[i] - mean) * inv, g[i], b[i]));
        size_t dst;
        if (mode == 0) dst = (size_t)grp * G + i;
        else {
            int t = i >> 8, c = i & 255;
            dst = ((size_t)(n * TT + t) * VV + v) * 256 + c;
        }
        if (wf) outf[dst] = val;
        oh[dst] = __float2half(val);
    }
}

// temporal attention split-K partials
__global__ __launch_bounds__(256) void att_t_part(
        const float* __restrict__ qd, const float* __restrict__ kd,
        float* __restrict__ pt) {
    int nm = blockIdx.x;
    int kb = blockIdx.y * 320;
    __shared__ float Qs[64][68], Ks[64][68];
    const float* qb = qd + (size_t)nm * TT * 1600;
    const float* kb_ = kd + (size_t)nm * TT * 1600;
    const int tid = threadIdx.x;
    const int tx = tid & 15, ty = tid >> 4;
    const int lr = tid >> 2, lc = (tid & 3) << 4;
    float acc[4][4] = {};
    for (int kc = kb; kc < kb + 320; kc += 64) {
#pragma unroll
        for (int j = 0; j < 4; j++) {
            float4 q4 = *(const float4*)(qb + (size_t)lr * 1600 + kc + lc + j * 4);
            float4 k4 = *(const float4*)(kb_ + (size_t)lr * 1600 + kc + lc + j * 4);
            Qs[lc + j*4 + 0][lr] = q4.x; Qs[lc + j*4 + 1][lr] = q4.y;
            Qs[lc + j*4 + 2][lr] = q4.z; Qs[lc + j*4 + 3][lr] = q4.w;
            Ks[lc + j*4 + 0][lr] = k4.x; Ks[lc + j*4 + 1][lr] = k4.y;
            Ks[lc + j*4 + 2][lr] = k4.z; Ks[lc + j*4 + 3][lr] = k4.w;
        }
        __syncthreads();
#pragma unroll 8
        for (int kk = 0; kk < 64; kk++) {
            float4 aq = *(const float4*)(&Qs[kk][ty << 2]);
            float4 bk = *(const float4*)(&Ks[kk][tx << 2]);
            float a[4] = {aq.x, aq.y, aq.z, aq.w};
            float b[4] = {bk.x, bk.y, bk.z, bk.w};
#pragma unroll
            for (int i = 0; i < 4; i++)
#pragma unroll
                for (int j = 0; j < 4; j++) acc[i][j] = fmaf(a[i], b[j], acc[i][j]);
        }
        __syncthreads();
    }
#pragma unroll
    for (int i = 0; i < 4; i++)
#pragma unroll
        for (int j = 0; j < 4; j++) {
            int t_ = (ty << 2) + i, q_ = (tx << 2) + j;
            atomicAdd(&pt[(size_t)nm * 4096 + t_ * 64 + q_], acc[i][j]);
        }
}

__global__ void att_t_fin(const float* __restrict__ pt, const float* __restrict__ alf,
                          const float* __restrict__ alb, float* __restrict__ attf,
                          float* __restrict__ attb) {
    int idx = blockIdx.x * 256 + threadIdx.x;
    if (idx >= 128 * 4096) return;
    int nm = idx >> 12, r = idx & 4095;
    int t = r >> 6, q = r & 63;
    int n = nm >> 2, m = nm & 3, s = m & 1, dir = m >> 1;
    float val = tanhf(pt[idx] * (1.f / 1600.f)) * (dir ? alb[s] : alf[s]);
    size_t o = ((size_t)(n * TT + q) * TT + t) * 2 + s;
    if (dir == 0) attf[o] = (q <= t) ? val : 0.f;
    else          attb[o] = (q >= t) ? val : 0.f;
}

// z apply: fp16 output
__global__ __launch_bounds__(256) void z2k(const float* __restrict__ y2t,
                                           const float* __restrict__ attf,
                                           const float* __restrict__ attb,
                                           __half* __restrict__ zh) {
    extern __shared__ float zs[];
    float* ys = zs;
    float* as_ = zs + 64 * 256;
    int b = blockIdx.x;
    int n = b / VV, v = b % VV;
    int tid = threadIdx.x;
    for (int i = tid; i < 64 * 256; i += 256) {
        int t = i >> 8, c = i & 255;
        ys[t * 256 + c] = y2t[((size_t)(n * TT + t) * VV + v) * 256 + c];
    }
    __syncthreads();
    int c = tid;
    for (int q = 0; q < TT; q++) {
        if (tid < 128) as_[tid] = attf[(size_t)n * 8192 + q * 128 + tid];
        else           as_[tid] = attb[(size_t)n * 8192 + q * 128 + (tid - 128)];
        __syncthreads();
        float f0 = 0.f, f1 = 0.f, b0 = 0.f, b1 = 0.f;
#pragma unroll 8
        for (int t = 0; t < TT; t++) {
            float yv = ys[t * 256 + c];
            f0 = fmaf(yv, as_[t * 2], f0);       f1 = fmaf(yv, as_[t * 2 + 1], f1);
            b0 = fmaf(yv, as_[128 + t * 2], b0); b1 = fmaf(yv, as_[128 + t * 2 + 1], b1);
        }
        size_t base = ((size_t)(n * TT + q) * VV + v) * 1024;
        *(uint32_t*)(zh + base + c * 2) = packh2(f0, f1);
        *(uint32_t*)(zh + base + 512 + c * 2) = packh2(b0, b1);
        __syncthreads();
    }
}

__global__ void final_kernel(const float* __restrict__ z2, const float* __restrict__ cv,
                             const float* __restrict__ bn_g, const float* __restrict__ bn_b,
                             const float* __restrict__ bn_m, const float* __restrict__ bn_v,
                             float* __restrict__ out) {
    size_t i = (size_t)blockIdx.x * 256 + threadIdx.x;
    int o = (int)(i & 255);
    size_t r = i >> 8;
    int v = (int)(r % VV);
    size_t r2 = r / VV;
    int t = (int)(r2 % TT);
    int n = (int)(r2 / TT);
    float c1 = fmaf((cv[i] - bn_m[o]) * rsqrtf(bn_v[o] + 1e-5f), bn_g[o], bn_b[o]);
    out[((size_t)(n * VV + v) * TT + t) * 256 + o] = gelu_f(z2[i] + c1);
}

// ------------------------------- launcher -----------------------------------
extern "C" void kernel_launch(void* const* d_in, const int* in_sizes, int n_in,
                              void* d_out, int out_size) {
    const float* x       = (const float*)d_in[0];
    const float* Wqk_s   = (const float*)d_in[1];
    const float* bqk_s   = (const float*)d_in[2];
    const float* alphas  = (const float*)d_in[3];
    const float* att0s   = (const float*)d_in[4];
    const float* Wo_s    = (const float*)d_in[5];
    const float* bo_s    = (const float*)d_in[6];
    const float* g_os    = (const float*)d_in[7];
    const float* b_os    = (const float*)d_in[8];
    const float* Wff_s   = (const float*)d_in[9];
    const float* bff_s   = (const float*)d_in[10];
    const float* g_ffs   = (const float*)d_in[11];
    const float* b_ffs   = (const float*)d_in[12];
    const float* Wqk_t   = (const float*)d_in[13];
    const float* bqk_t   = (const float*)d_in[14];
    const float* alphat_f= (const float*)d_in[15];
    const float* alphat_b= (const float*)d_in[16];
    const float* Wo_t    = (const float*)d_in[17];
    const float* bo_t    = (const float*)d_in[18];
    const float* g_ot    = (const float*)d_in[19];
    const float* b_ot    = (const float*)d_in[20];
    const float* Wff_t   = (const float*)d_in[21];
    const float* bff_t   = (const float*)d_in[22];
    const float* g_fft   = (const float*)d_in[23];
    const float* b_fft   = (const float*)d_in[24];
    const float* conv_w  = (const float*)d_in[25];
    const float* conv_b  = (const float*)d_in[26];
    const float* bn_g    = (const float*)d_in[27];
    const float* bn_b    = (const float*)d_in[28];
    const float* bn_m    = (const float*)d_in[29];
    const float* bn_v    = (const float*)d_in[30];
    float* out = (float*)d_out;

    void *pB, *pH, *pY1, *pY2, *pZ2, *pAS, *pAF, *pAB, *pWH, *pPS, *pPT;
    void *pAH, *pXH, *pY1H, *pY2H, *pZ2H;
    cudaGetSymbolAddress(&pB,  g_bufB);
    cudaGetSymbolAddress(&pH,  g_h);
    cudaGetSymbolAddress(&pY1, g_y1);
    cudaGetSymbolAddress(&pY2, g_y2);
    cudaGetSymbolAddress(&pZ2, g_z2);
    cudaGetSymbolAddress(&pAS, g_atts);
    cudaGetSymbolAddress(&pAF, g_attf);
    cudaGetSymbolAddress(&pAB, g_attb);
    cudaGetSymbolAddress(&pPS, g_ps);
    cudaGetSymbolAddress(&pPT, g_pt);
    cudaGetSymbolAddress(&pWH, g_wh);
    cudaGetSymbolAddress(&pAH, g_ah);
    cudaGetSymbolAddress(&pXH, g_xh);
    cudaGetSymbolAddress(&pY1H, g_y1h);
    cudaGetSymbolAddress(&pY2H, g_y2h);
    cudaGetSymbolAddress(&pZ2H, g_z2h);
    float* bufB = (float*)pB;
    float* h    = (float*)pH;  float* y1   = (float*)pY1;
    float* y2   = (float*)pY2; float* z2b  = (float*)pZ2;
    float* atts = (float*)pAS; float* attf = (float*)pAF;
    float* attb = (float*)pAB;
    float* ps   = (float*)pPS; float* pt   = (float*)pPT;
    __half* wh  = (__half*)pWH;
    __half* ah  = (__half*)pAH;
    __half* xh  = (__half*)pXH;
    __half* y1h = (__half*)pY1H;
    __half* y2h = (__half*)pY2H;
    __half* z2h = (__half*)pZ2H;

    cudaFuncSetAttribute(gemm_h, cudaFuncAttributeMaxDynamicSharedMemorySize, GSM);
    cudaFuncSetAttribute(conv_h, cudaFuncAttributeMaxDynamicSharedMemorySize, GSM);
    cudaFuncSetAttribute(z2k, cudaFuncAttributeMaxDynamicSharedMemorySize, (64*256 + 256) * 4);
    cudaFuncSetAttribute(deint_s2, cudaFuncAttributeMaxDynamicSharedMemorySize, DS_SMEM);
    cudaFuncSetAttribute(deint_t2, cudaFuncAttributeMaxDynamicSharedMemorySize, DT_SMEM);

    dim3 blk(256);
    const int MB = RTOT / 128;   // 400
    const int WHALF = WTOT / 2;

    prep_x<<<(XITEMS + 255) / 256, blk>>>(x, xh);
    prep_w<<<(WHALF + 255) / 256, blk>>>(Wqk_s, Wo_s, Wff_s, Wqk_t, Wo_t, Wff_t,
                                         conv_w, wh, 0, WHALF);
    prep_w<<<(WHALF + 255) / 256, blk>>>(Wqk_s, Wo_s, Wff_s, Wqk_t, Wo_t, Wff_t,
                                         conv_w, wh, WHALF, WTOT - WHALF);
    cudaMemsetAsync(ps, 0, 96 * 625 * sizeof(float));
    cudaMemsetAsync(pt, 0, 128 * 4096 * sizeof(float));

    // Stage 1: spatial
    gemm_h<<<dim3(3, MB), blk, GSM>>>(xh, wh + OFF_QKS, bqk_s, bufB, RTOT, 384, 256);
    deint_s2<<<NN * VV * 2, blk, DS_SMEM>>>(bufB, h, y1);
    att_s_part<<<dim3(96, 8), 128>>>(h, y1, ps);
    att_s_fin<<<(96 * 625 + 255) / 256, blk>>>(ps, alphas, att0s, atts);
    ys2<<<NN * TT, blk>>>(x, atts, ah);
    gemm_h<<<dim3(2, MB), blk, GSM>>>(ah, wh + OFF_WOS, bo_s, h, RTOT, 256, 768);
    ln2<<<NN*VV, blk>>>(h, x, g_os, b_os, y1, y1h, TT*256, 0, 0);
    gemm_h<<<dim3(2, MB), blk, GSM>>>(y1h, wh + OFF_FFS, bff_s, h, RTOT, 256, 256);
    ln2<<<NN*VV, blk>>>(h, x, g_ffs, b_ffs, y2, y2h, TT*256, 1, 1);

    // Stage 2: temporal
    gemm_h<<<dim3(4, MB), blk, GSM>>>(y2h, wh + OFF_QKT, bqk_t, bufB, RTOT, 512, 256);
    deint_t2<<<NN * TT, blk, DT_SMEM>>>(bufB, h, y1);
    att_t_part<<<dim3(128, 5), blk>>>(h, y1, pt);
    att_t_fin<<<(128 * 4096 + 255) / 256, blk>>>(pt, alphat_f, alphat_b, attf, attb);
    z2k<<<NN * VV, blk, (64*256 + 256) * 4>>>(y2, attf, attb, ah);
    gemm_h<<<dim3(2, MB), blk, GSM>>>(ah, wh + OFF_WOT, bo_t, h, RTOT, 256, 1024);
    ln2<<<NN*TT, blk>>>(h, y2, g_ot, b_ot, y1, y1h, VV*256, 0, 0);
    gemm_h<<<dim3(2, MB), blk, GSM>>>(y1h, wh + OFF_FFT, bff_t, h, RTOT, 256, 256);
    ln2<<<NN*TT, blk>>>(h, y2, g_fft, b_fft, z2b, z2h, VV*256, 0, 1);

    // Stage 3: conv + BN + gelu + transpose
    conv_h<<<dim3(2, MB), blk, GSM>>>(z2h, wh + OFF_CNV, conv_b, h);
    final_kernel<<<RTOT, blk>>>(z2b, h, bn_g, bn_b, bn_m, bn_v, out);
}

// round 16
// speedup vs baseline: 1.2726x; 1.0683x over previous
#include <cuda_runtime.h>
#include <cuda_fp16.h>
#include <math.h>
#include <stdint.h>

#define NN 32
#define VV 25
#define TT 64
#define RTOT (NN*VV*TT)   /* 51200 */

// ------------------------- scratch (device globals) -------------------------
__device__ float g_h   [(size_t)RTOT * 256];
__device__ float g_y1  [(size_t)RTOT * 256];
__device__ float g_y2  [(size_t)RTOT * 256];
__device__ float g_z2  [(size_t)RTOT * 256];
__device__ float g_atts[NN*VV*VV*3];
__device__ float g_attf[NN*TT*TT*2];   // transposed layout [n][q][t][s]
__device__ float g_attb[NN*TT*TT*2];
__device__ float g_ps  [96*625];
__device__ float g_pt  [128*64*64];
// fp16 buffers (16B-aligned for cp.async)
__device__ __align__(128) __half g_bufBh[(size_t)RTOT * 512];
__device__ __align__(128) __half g_qh [13107200];
__device__ __align__(128) __half g_kh [13107200];
__device__ __align__(128) __half g_ah [(size_t)RTOT * 1024];
__device__ __align__(128) __half g_xh [(size_t)RTOT * 256];
__device__ __align__(128) __half g_y1h[(size_t)RTOT * 256];
__device__ __align__(128) __half g_y2h[(size_t)RTOT * 256];
__device__ __align__(128) __half g_z2h[(size_t)RTOT * 256];
#define WTOT 1277952
__device__ __align__(128) __half g_wh[WTOT];
#define OFF_QKS 0         /* K=256  N=384  */
#define OFF_WOS 98304     /* K=768  N=256  */
#define OFF_FFS 294912    /* K=256  N=256  */
#define OFF_QKT 360448    /* K=256  N=512  */
#define OFF_WOT 491520    /* K=1024 N=256  */
#define OFF_FFT 753664    /* K=256  N=256  */
#define OFF_CNV 819200    /* K=1792 N=256  */

__device__ __forceinline__ float gelu_f(float x) {
    return 0.5f * x * (1.0f + erff(x * 0.7071067811865475f));
}
__device__ __forceinline__ uint32_t packh2(float a, float b) {
    __half2 h = __floats2half2_rn(a, b);
    return *(uint32_t*)&h;
}
__device__ __forceinline__ uint32_t smem_u32(const void* p) {
    uint32_t a;
    asm("{ .reg .u64 t; cvta.to.shared.u64 t, %1; cvt.u32.u64 %0, t; }" : "=r"(a) : "l"(p));
    return a;
}
__device__ __forceinline__ void ldm4(uint32_t &r0, uint32_t &r1, uint32_t &r2,
                                     uint32_t &r3, uint32_t a) {
    asm volatile("ldmatrix.sync.aligned.m8n8.x4.shared.b16 {%0,%1,%2,%3}, [%4];"
        : "=r"(r0), "=r"(r1), "=r"(r2), "=r"(r3) : "r"(a));
}
__device__ __forceinline__ void mma16816h(float* c, const uint32_t* a, const uint32_t* b) {
    asm volatile(
        "mma.sync.aligned.m16n8k16.row.col.f32.f16.f16.f32 "
        "{%0,%1,%2,%3}, {%4,%5,%6,%7}, {%8,%9}, {%0,%1,%2,%3};"
        : "+f"(c[0]), "+f"(c[1]), "+f"(c[2]), "+f"(c[3])
        : "r"(a[0]), "r"(a[1]), "r"(a[2]), "r"(a[3]), "r"(b[0]), "r"(b[1]));
}
__device__ __forceinline__ void cpa16(uint32_t dst, const void* src) {
    asm volatile("cp.async.cg.shared.global [%0], [%1], 16;" :: "r"(dst), "l"(src));
}
__device__ __forceinline__ void cpa16z(uint32_t dst, const void* src, int sz) {
    asm volatile("cp.async.cg.shared.global [%0], [%1], 16, %2;" :: "r"(dst), "l"(src), "r"(sz));
}
#define CPA_COMMIT() asm volatile("cp.async.commit_group;" ::: "memory")
#define CPA_WAIT1() asm volatile("cp.async.wait_group 1;" ::: "memory")
#define CPA_WAIT0() asm volatile("cp.async.wait_group 0;" ::: "memory")

// smem swizzle for 128B rows (64 fp16): 16B chunk ch of row r at (ch ^ (r&7))*16
#define SWZ8(row, ch) ((uint32_t)((row) * 128 + (((ch) ^ ((row) & 7)) << 4)))

// == fp16 HMMA GEMM (single-term): 128x128 tile, warp 64x32, k-chunk 64 ======
// C = A[M,K] @ B[K,N] + bias; B stored [N][K]. h16 selects fp16 or fp32 C.
#define GSM (2*32768)
__global__ __launch_bounds__(256, 2) void gemm_h(
        const __half* __restrict__ A, const __half* __restrict__ B,
        const float* __restrict__ bias, float* __restrict__ Cf,
        __half* __restrict__ Ch, int h16, int M, int N, int K) {
    extern __shared__ char sm[];
    const uint32_t sbase = smem_u32(sm);
    const int tid = threadIdx.x, lane = tid & 31, w = tid >> 5;
    const int wm = w & 1, wn = w >> 1;
    const int bm = blockIdx.y << 7, bn = blockIdx.x << 7;
    float acc[4][4][4];
#pragma unroll
    for (int i = 0; i < 4; i++)
#pragma unroll
        for (int j = 0; j < 4; j++)
#pragma unroll
            for (int q = 0; q < 4; q++) acc[i][j][q] = 0.f;
    const int nch = K >> 6;

    auto load_stage = [&](int c) {
        uint32_t st = sbase + (c & 1) * 32768;
        const int k0 = c << 6;
#pragma unroll
        for (int j = 0; j < 4; j++) {
            int f = j * 256 + tid;
            int row = f >> 3, ch = f & 7;
            uint32_t off = SWZ8(row, ch);
            cpa16(st + off,         A + (size_t)(bm + row) * K + k0 + ch * 8);
            cpa16(st + 16384 + off, B + (size_t)(bn + row) * K + k0 + ch * 8);
        }
        CPA_COMMIT();
    };
    load_stage(0);
    for (int c = 0; c < nch; c++) {
        if (c + 1 < nch) { load_stage(c + 1); CPA_WAIT1(); }
        else CPA_WAIT0();
        __syncthreads();
        const uint32_t sA = sbase + (c & 1) * 32768;
        const uint32_t sB = sA + 16384;
#pragma unroll
        for (int kk = 0; kk < 4; kk++) {
            uint32_t af[4][4];
            const int arow = wm * 64 + (lane & 15);
            const int achunk = kk * 2 + (lane >> 4);
#pragma unroll
            for (int mi = 0; mi < 4; mi++) {
                int row = arow + mi * 16;
                ldm4(af[mi][0], af[mi][1], af[mi][2], af[mi][3], sA + SWZ8(row, achunk));
            }
            const int bchunk = kk * 2 + ((lane >> 3) & 1);
            uint32_t bf[4][2];
#pragma unroll
            for (int ng = 0; ng < 2; ng++) {
                int brow = wn * 32 + ng * 16 + ((lane & 16) >> 1) + (lane & 7);
                ldm4(bf[2*ng][0], bf[2*ng][1], bf[2*ng+1][0], bf[2*ng+1][1],
                     sB + SWZ8(brow, bchunk));
            }
#pragma unroll
            for (int mi = 0; mi < 4; mi++)
#pragma unroll
                for (int nf = 0; nf < 4; nf++)
                    mma16816h(acc[mi][nf], af[mi], bf[nf]);
        }
        __syncthreads();
    }
    const int gid = lane >> 2, tig = lane & 3;
#pragma unroll
    for (int mi = 0; mi < 4; mi++)
#pragma unroll
        for (int nf = 0; nf < 4; nf++) {
            int col = bn + wn * 32 + nf * 8 + tig * 2;
            float b0v = bias[col], b1v = bias[col + 1];
            int r0 = bm + wm * 64 + mi * 16 + gid;
            if (h16) {
                *(uint32_t*)(Ch + (size_t)r0 * N + col) =
                    packh2(acc[mi][nf][0] + b0v, acc[mi][nf][1] + b1v);
                *(uint32_t*)(Ch + (size_t)(r0 + 8) * N + col) =
                    packh2(acc[mi][nf][2] + b0v, acc[mi][nf][3] + b1v);
            } else {
                *(float2*)(Cf + (size_t)r0 * N + col) =
                    make_float2(acc[mi][nf][0] + b0v, acc[mi][nf][1] + b1v);
                *(float2*)(Cf + (size_t)(r0 + 8) * N + col) =
                    make_float2(acc[mi][nf][2] + b0v, acc[mi][nf][3] + b1v);
            }
        }
}

// == conv + BN + gelu + residual + transpose fused: K=1792, warp 64x32 =======
__global__ __launch_bounds__(256, 2) void conv_h(
        const __half* __restrict__ Z, const __half* __restrict__ B,
        const float* __restrict__ cbias, const float* __restrict__ z2,
        const float* __restrict__ bng, const float* __restrict__ bnb,
        const float* __restrict__ bnm, const float* __restrict__ bnv,
        float* __restrict__ out) {
    const int N = 256, K = 1792;
    extern __shared__ char sm[];
    const uint32_t sbase = smem_u32(sm);
    const int tid = threadIdx.x, lane = tid & 31, w = tid >> 5;
    const int wm = w & 1, wn = w >> 1;
    const int bm = blockIdx.y << 7, bn = blockIdx.x << 7;
    float acc[4][4][4];
#pragma unroll
    for (int i = 0; i < 4; i++)
#pragma unroll
        for (int j = 0; j < 4; j++)
#pragma unroll
            for (int q = 0; q < 4; q++) acc[i][j][q] = 0.f;
    const int nch = K >> 6;   // 28

    auto load_stage = [&](int c) {
        uint32_t st = sbase + (c & 1) * 32768;
        const int k0 = c << 6;
        const int dt = (k0 >> 8) - 3;
        const int iio = k0 & 255;
#pragma unroll
        for (int j = 0; j < 4; j++) {
            int f = j * 256 + tid;
            int row = f >> 3, ch = f & 7;
            uint32_t off = SWZ8(row, ch);
            int grow = bm + row;
            int t = (grow / VV) % TT;
            int tt = t + dt;
            int ok = (tt >= 0 && tt < TT);
            size_t srcoff = ok ? ((size_t)grow + (size_t)dt * VV) * 256 + iio + ch * 8 : 0;
            cpa16z(st + off, Z + srcoff, ok ? 16 : 0);
            cpa16(st + 16384 + off, B + (size_t)(bn + row) * K + k0 + ch * 8);
        }
        CPA_COMMIT();
    };
    load_stage(0);
    for (int c = 0; c < nch; c++) {
        if (c + 1 < nch) { load_stage(c + 1); CPA_WAIT1(); }
        else CPA_WAIT0();
        __syncthreads();
        const uint32_t sA = sbase + (c & 1) * 32768;
        const uint32_t sB = sA + 16384;
#pragma unroll
        for (int kk = 0; kk < 4; kk++) {
            uint32_t af[4][4];
            const int arow = wm * 64 + (lane & 15);
            const int achunk = kk * 2 + (lane >> 4);
#pragma unroll
            for (int mi = 0; mi < 4; mi++) {
                int row = arow + mi * 16;
                ldm4(af[mi][0], af[mi][1], af[mi][2], af[mi][3], sA + SWZ8(row, achunk));
            }
            const int bchunk = kk * 2 + ((lane >> 3) & 1);
            uint32_t bf[4][2];
#pragma unroll
            for (int ng = 0; ng < 2; ng++) {
                int brow = wn * 32 + ng * 16 + ((lane & 16) >> 1) + (lane & 7);
                ldm4(bf[2*ng][0], bf[2*ng][1], bf[2*ng+1][0], bf[2*ng+1][1],
                     sB + SWZ8(brow, bchunk));
            }
#pragma unroll
            for (int mi = 0; mi < 4; mi++)
#pragma unroll
                for (int nf = 0; nf < 4; nf++)
                    mma16816h(acc[mi][nf], af[mi], bf[nf]);
        }
        __syncthreads();
    }
    // fused epilogue: out[n,v,t,col] = gelu(z2[row,col] + BN(acc + cbias))
    const int gid = lane >> 2, tig = lane & 3;
#pragma unroll
    for (int mi = 0; mi < 4; mi++)
#pragma unroll
        for (int nf = 0; nf < 4; nf++) {
            int col = bn + wn * 32 + nf * 8 + tig * 2;
            float cb0 = cbias[col], cb1 = cbias[col + 1];
            float s0 = rsqrtf(bnv[col] + 1e-5f) * bng[col];
            float s1 = rsqrtf(bnv[col + 1] + 1e-5f) * bng[col + 1];
            float m0 = bnm[col], m1 = bnm[col + 1];
            float bb0 = bnb[col], bb1 = bnb[col + 1];
#pragma unroll
            for (int rr = 0; rr < 2; rr++) {
                int grow = bm + wm * 64 + mi * 16 + gid + rr * 8;
                int n = grow / (TT * VV);
                int rem = grow - n * TT * VV;
                int t = rem / VV, v = rem - t * VV;
                float z0 = z2[(size_t)grow * 256 + col];
                float z1 = z2[(size_t)grow * 256 + col + 1];
                float a0 = acc[mi][nf][rr * 2 + 0], a1 = acc[mi][nf][rr * 2 + 1];
                float c0 = fmaf(a0 + cb0 - m0, s0, bb0);
                float c1 = fmaf(a1 + cb1 - m1, s1, bb1);
                *(float2*)(out + ((size_t)(n * VV + v) * TT + t) * 256 + col) =
                    make_float2(gelu_f(z0 + c0), gelu_f(z1 + c1));
            }
        }
}

// ---------------- prep kernels (x convert; weight fp16 transpose) -----------
#define XITEMS 3276800
__global__ void prep_x(const float* __restrict__ x, __half* __restrict__ xh) {
    size_t idx = (size_t)blockIdx.x * 256 + threadIdx.x;
    if (idx >= XITEMS) return;
    size_t i = idx * 4;
    float4 v = *(const float4*)(x + i);
    *(uint2*)(xh + i) = make_uint2(packh2(v.x, v.y), packh2(v.z, v.w));
}
__global__ void prep_w(
        const float* __restrict__ Wqks, const float* __restrict__ Wos,
        const float* __restrict__ Wffs, const float* __restrict__ Wqkt,
        const float* __restrict__ Wot,  const float* __restrict__ Wfft,
        const float* __restrict__ Wcnv,
        __half* __restrict__ wh, int jbase, int jcount) {
    int li = blockIdx.x * 256 + threadIdx.x;
    if (li >= jcount) return;
    long j = (long)jbase + li;
    const float* W; int K, N, off; int isconv = 0;
    if (j < 98304)                    { W = Wqks; K = 256;  N = 384; off = OFF_QKS; }
    else if ((j -= 98304)  < 196608)  { W = Wos;  K = 768;  N = 256; off = OFF_WOS; }
    else if ((j -= 196608) < 65536)   { W = Wffs; K = 256;  N = 256; off = OFF_FFS; }
    else if ((j -= 65536)  < 131072)  { W = Wqkt; K = 256;  N = 512; off = OFF_QKT; }
    else if ((j -= 131072) < 262144)  { W = Wot;  K = 1024; N = 256; off = OFF_WOT; }
    else if ((j -= 262144) < 65536)   { W = Wfft; K = 256;  N = 256; off = OFF_FFT; }
    else if ((j -= 65536)  < 458752)  { W = Wcnv; K = 1792; N = 256; off = OFF_CNV; isconv = 1; }
    else return;
    float v = W[j];
    size_t dst;
    if (isconv) {
        int o = (int)(j / 1792), r = (int)(j % 1792);
        int ii = r / 7, kw = r % 7;
        dst = (size_t)off + (size_t)o * 1792 + kw * 256 + ii;
    } else {
        int k = (int)(j / N), n = (int)(j % N);
        dst = (size_t)off + (size_t)n * K + k;
    }
    wh[dst] = __float2half(v);
}

// ------ deint_s: fp16 in/out, smem-staged. block per (n,u,t-half) -----------
#define DS_SMEM (6 * 2056 * 2)
__global__ __launch_bounds__(256) void deint_s2(const __half* __restrict__ qk,
                                                __half* __restrict__ qT,
                                                __half* __restrict__ kT) {
    extern __shared__ __half smsh[];
    int b = blockIdx.x;
    int th = b & 1;
    int u = (b >> 1) % VV;
    int n = b / (VV * 2);
    int t0 = th << 5;
    const __half* src = qk + ((size_t)(n * VV + u) * TT + t0) * 384;
    for (int i = threadIdx.x; i < 32 * 384; i += 256) {
        int tt = i / 384, col = i % 384;
        int ci = col / 6, r = col % 6;
        smsh[r * 2056 + tt * 64 + ci] = src[i];
    }
    __syncthreads();
#pragma unroll
    for (int p = 0; p < 6; p++) {
        int s = (p < 3) ? p : p - 3;
        __half* dst = ((p < 3) ? qT : kT) +
                      (((size_t)(n * 3 + s) * VV + u) << 12) + (size_t)t0 * 64;
        for (int i = threadIdx.x; i < 2048; i += 256)
            dst[i] = smsh[p * 2056 + i];
    }
}

// ------ deint_t: fp16 in/out, smem-staged. block per (n,t) -------------------
#define DT_SMEM (8 * 1672 * 2)
__global__ __launch_bounds__(256) void deint_t2(const __half* __restrict__ qkt,
                                                __half* __restrict__ qd,
                                                __half* __restrict__ kd) {
    extern __shared__ __half smth[];
    int b = blockIdx.x;
    int t = b % TT, n = b / TT;
    const __half* src = qkt + ((size_t)(n * TT + t) * VV) * 512;
    for (int i = threadIdx.x; i < 25 * 512; i += 256) {
        int v = i >> 9, col = i & 511;
        int ci = col >> 3, j = col & 7;
        smth[j * 1672 + v * 64 + ci] = src[i];
    }
    __syncthreads();
#pragma unroll
    for (int p = 0; p < 8; p++) {
        int m = p & 3;
        __half* dst = ((p < 4) ? qd : kd) + ((size_t)(n * 4 + m) * TT + t) * 1600;
        for (int i = threadIdx.x; i < 1600; i += 256)
            dst[i] = smth[p * 1672 + i];
    }
}

// spatial attention split-K partials (fp16 inputs)
__global__ __launch_bounds__(128) void att_s_part(
        const __half* __restrict__ qT, const __half* __restrict__ kT,
        float* __restrict__ ps) {
    int ns = blockIdx.x;
    int kc0 = blockIdx.y << 9;
    __shared__ float qs[25][132], ks[25][132];
    const __half* qb = qT + ((size_t)ns * VV << 12);
    const __half* kb = kT + ((size_t)ns * VV << 12);
    int t = threadIdx.x;
    int u0 = (t / 25) * 5, v = t % 25;
    float acc[5] = {0.f, 0.f, 0.f, 0.f, 0.f};
    for (int kc = kc0; kc < kc0 + 512; kc += 128) {
        for (int i = t; i < 25 * 128; i += 128) {
            int uu = i >> 7, e = i & 127;
            qs[uu][e] = __half2float(qb[((size_t)uu << 12) + kc + e]);
            ks[uu][e] = __half2float(kb[((size_t)uu << 12) + kc + e]);
        }
        __syncthreads();
        if (t < 125) {
#pragma unroll 4
            for (int e = 0; e < 128; e++) {
                float kv = ks[v][e];
                acc[0] = fmaf(qs[u0 + 0][e], kv, acc[0]);
                acc[1] = fmaf(qs[u0 + 1][e], kv, acc[1]);
                acc[2] = fmaf(qs[u0 + 2][e], kv, acc[2]);
                acc[3] = fmaf(qs[u0 + 3][e], kv, acc[3]);
                acc[4] = fmaf(qs[u0 + 4][e], kv, acc[4]);
            }
        }
        __syncthreads();
    }
    if (t < 125) {
#pragma unroll
        for (int i = 0; i < 5; i++)
            atomicAdd(&ps[(size_t)ns * 625 + (u0 + i) * 25 + v], acc[i]);
    }
}

__global__ void att_s_fin(const float* __restrict__ ps, const float* __restrict__ alphas,
                          const float* __restrict__ att0, float* __restrict__ att) {
    int idx = blockIdx.x * 256 + threadIdx.x;
    if (idx >= 96 * 625) return;
    int ns = idx / 625, r = idx % 625;
    int n = ns / 3, s = ns % 3, u = r / 25, v = r % 25;
    att[((size_t)(n * VV + u) * VV + v) * 3 + s] =
        tanhf(ps[idx] * (1.f / 4096.f)) * alphas[s] + att0[((size_t)u * VV + v) * 3 + s];
}

// y_s: block per (n,t); fp16 output
__global__ __launch_bounds__(256) void ys2(const float* __restrict__ x,
                                           const float* __restrict__ att,
                                           __half* __restrict__ yh) {
    __shared__ float xs[25][256];
    __shared__ float as_[25 * 25 * 3];
    int b = blockIdx.x;
    int n = b >> 6, t = b & 63;
    int tid = threadIdx.x;
    for (int i = tid; i < 25 * 256; i += 256) {
        int u = i >> 8, c = i & 255;
        xs[u][c] = x[((size_t)(n * VV + u) * TT + t) * 256 + c];
    }
    for (int i = tid; i < 1875; i += 256) as_[i] = att[(size_t)n * 1875 + i];
    __syncthreads();
    int c = tid;
#pragma unroll 1
    for (int v = 0; v < VV; v++) {
        float a0 = 0.f, a1 = 0.f, a2 = 0.f;
#pragma unroll
        for (int u = 0; u < VV; u++) {
            float xv = xs[u][c];
            a0 = fmaf(xv, as_[(u * VV + v) * 3 + 0], a0);
            a1 = fmaf(xv, as_[(u * VV + v) * 3 + 1], a1);
            a2 = fmaf(xv, as_[(u * VV + v) * 3 + 2], a2);
        }
        size_t base = ((size_t)(n * VV + v) * TT + t) * 768 + c * 3;
        yh[base]     = __float2half(a0);
        yh[base + 1] = __float2half(a1);
        yh[base + 2] = __float2half(a2);
    }
}

// LN + residual + gelu; writes fp16 (+ optional fp32)
__global__ void ln2(const float* __restrict__ h, const float* __restrict__ res,
                    const float* __restrict__ g, const float* __restrict__ b,
                    float* __restrict__ outf, __half* __restrict__ oh,
                    int G, int mode, int wf) {
    int grp = blockIdx.x;
    const float* hp = h + (size_t)grp * G;
    const float* rp = res + (size_t)grp * G;
    float s = 0.f, sq = 0.f;
    for (int i = threadIdx.x; i < G; i += blockDim.x) {
        float v = hp[i]; s += v; sq = fmaf(v, v, sq);
    }
    for (int o = 16; o; o >>= 1) {
        s += __shfl_down_sync(0xffffffffu, s, o);
        sq += __shfl_down_sync(0xffffffffu, sq, o);
    }
    __shared__ float ss[8], sqs[8];
    __shared__ float mean_s, inv_s;
    int w = threadIdx.x >> 5;
    if ((threadIdx.x & 31) == 0) { ss[w] = s; sqs[w] = sq; }
    __syncthreads();
    if (threadIdx.x == 0) {
        float S = 0.f, Q = 0.f;
        for (int i = 0; i < 8; i++) { S += ss[i]; Q += sqs[i]; }
        float mean = S / G;
        float var = Q / G - mean * mean;
        mean_s = mean; inv_s = rsqrtf(var + 1e-5f);
    }
    __syncthreads();
    float mean = mean_s, inv = inv_s;
    int n = 0, v = 0;
    if (mode == 1) { n = grp / VV; v = grp % VV; }
    for (int i = threadIdx.x; i < G; i += blockDim.x) {
        float val = gelu_f(rp[i] + fmaf((hp[i] - mean) * inv, g[i], b[i]));
        size_t dst;
        if (mode == 0) dst = (size_t)grp * G + i;
        else {
            int t = i >> 8, c = i & 255;
            dst = ((size_t)(n * TT + t) * VV + v) * 256 + c;
        }
        if (wf) outf[dst] = val;
        oh[dst] = __float2half(val);
    }
}

// temporal attention split-K partials (fp16 inputs)
__global__ __launch_bounds__(256) void att_t_part(
        const __half* __restrict__ qd, const __half* __restrict__ kd,
        float* __restrict__ pt) {
    int nm = blockIdx.x;
    int kb = blockIdx.y * 320;
    __shared__ float Qs[64][68], Ks[64][68];
    const __half* qb = qd + (size_t)nm * TT * 1600;
    const __half* kb_ = kd + (size_t)nm * TT * 1600;
    const int tid = threadIdx.x;
    const int tx = tid & 15, ty = tid >> 4;
    const int lr = tid >> 2, lc = (tid & 3) << 4;
    float acc[4][4] = {};
    for (int kc = kb; kc < kb + 320; kc += 64) {
        const uint4* qp = (const uint4*)(qb + (size_t)lr * 1600 + kc + lc);
        const uint4* kp = (const uint4*)(kb_ + (size_t)lr * 1600 + kc + lc);
#pragma unroll
        for (int hh = 0; hh < 2; hh++) {
            uint4 qv = qp[hh], kv = kp[hh];
            const __half2* hq = (const __half2*)&qv;
            const __half2* hk = (const __half2*)&kv;
#pragma unroll
            for (int e = 0; e < 4; e++) {
                float2 fq = __half22float2(hq[e]);
                float2 fk = __half22float2(hk[e]);
                int base = lc + hh * 8 + e * 2;
                Qs[base][lr] = fq.x;     Qs[base + 1][lr] = fq.y;
                Ks[base][lr] = fk.x;     Ks[base + 1][lr] = fk.y;
            }
        }
        __syncthreads();
#pragma unroll 8
        for (int kk = 0; kk < 64; kk++) {
            float4 aq = *(const float4*)(&Qs[kk][ty << 2]);
            float4 bk = *(const float4*)(&Ks[kk][tx << 2]);
            float a[4] = {aq.x, aq.y, aq.z, aq.w};
            float b[4] = {bk.x, bk.y, bk.z, bk.w};
#pragma unroll
            for (int i = 0; i < 4; i++)
#pragma unroll
                for (int j = 0; j < 4; j++) acc[i][j] = fmaf(a[i], b[j], acc[i][j]);
        }
        __syncthreads();
    }
#pragma unroll
    for (int i = 0; i < 4; i++)
#pragma unroll
        for (int j = 0; j < 4; j++) {
            int t_ = (ty << 2) + i, q_ = (tx << 2) + j;
            atomicAdd(&pt[(size_t)nm * 4096 + t_ * 64 + q_], acc[i][j]);
        }
}

__global__ void att_t_fin(const float* __restrict__ pt, const float* __restrict__ alf,
                          const float* __restrict__ alb, float* __restrict__ attf,
                          float* __restrict__ attb) {
    int idx = blockIdx.x * 256 + threadIdx.x;
    if (idx >= 128 * 4096) return;
    int nm = idx >> 12, r = idx & 4095;
    int t = r >> 6, q = r & 63;
    int n = nm >> 2, m = nm & 3, s = m & 1, dir = m >> 1;
    float val = tanhf(pt[idx] * (1.f / 1600.f)) * (dir ? alb[s] : alf[s]);
    size_t o = ((size_t)(n * TT + q) * TT + t) * 2 + s;
    if (dir == 0) attf[o] = (q <= t) ? val : 0.f;
    else          attb[o] = (q >= t) ? val : 0.f;
}

// z apply: fp16 output
__global__ __launch_bounds__(256) void z2k(const float* __restrict__ y2t,
                                           const float* __restrict__ attf,
                                           const float* __restrict__ attb,
                                           __half* __restrict__ zh) {
    extern __shared__ float zs[];
    float* ys = zs;
    float* as_ = zs + 64 * 256;
    int b = blockIdx.x;
    int n = b / VV, v = b % VV;
    int tid = threadIdx.x;
    for (int i = tid; i < 64 * 256; i += 256) {
        int t = i >> 8, c = i & 255;
        ys[t * 256 + c] = y2t[((size_t)(n * TT + t) * VV + v) * 256 + c];
    }
    __syncthreads();
    int c = tid;
    for (int q = 0; q < TT; q++) {
        if (tid < 128) as_[tid] = attf[(size_t)n * 8192 + q * 128 + tid];
        else           as_[tid] = attb[(size_t)n * 8192 + q * 128 + (tid - 128)];
        __syncthreads();
        float f0 = 0.f, f1 = 0.f, b0 = 0.f, b1 = 0.f;
#pragma unroll 8
        for (int t = 0; t < TT; t++) {
            float yv = ys[t * 256 + c];
            f0 = fmaf(yv, as_[t * 2], f0);       f1 = fmaf(yv, as_[t * 2 + 1], f1);
            b0 = fmaf(yv, as_[128 + t * 2], b0); b1 = fmaf(yv, as_[128 + t * 2 + 1], b1);
        }
        size_t base = ((size_t)(n * TT + q) * VV + v) * 1024;
        *(uint32_t*)(zh + base + c * 2) = packh2(f0, f1);
        *(uint32_t*)(zh + base + 512 + c * 2) = packh2(b0, b1);
        __syncthreads();
    }
}

// ------------------------------- launcher -----------------------------------
extern "C" void kernel_launch(void* const* d_in, const int* in_sizes, int n_in,
                              void* d_out, int out_size) {
    const float* x       = (const float*)d_in[0];
    const float* Wqk_s   = (const float*)d_in[1];
    const float* bqk_s   = (const float*)d_in[2];
    const float* alphas  = (const float*)d_in[3];
    const float* att0s   = (const float*)d_in[4];
    const float* Wo_s    = (const float*)d_in[5];
    const float* bo_s    = (const float*)d_in[6];
    const float* g_os    = (const float*)d_in[7];
    const float* b_os    = (const float*)d_in[8];
    const float* Wff_s   = (const float*)d_in[9];
    const float* bff_s   = (const float*)d_in[10];
    const float* g_ffs   = (const float*)d_in[11];
    const float* b_ffs   = (const float*)d_in[12];
    const float* Wqk_t   = (const float*)d_in[13];
    const float* bqk_t   = (const float*)d_in[14];
    const float* alphat_f= (const float*)d_in[15];
    const float* alphat_b= (const float*)d_in[16];
    const float* Wo_t    = (const float*)d_in[17];
    const float* bo_t    = (const float*)d_in[18];
    const float* g_ot    = (const float*)d_in[19];
    const float* b_ot    = (const float*)d_in[20];
    const float* Wff_t   = (const float*)d_in[21];
    const float* bff_t   = (const float*)d_in[22];
    const float* g_fft   = (const float*)d_in[23];
    const float* b_fft   = (const float*)d_in[24];
    const float* conv_w  = (const float*)d_in[25];
    const float* conv_b  = (const float*)d_in[26];
    const float* bn_g    = (const float*)d_in[27];
    const float* bn_b    = (const float*)d_in[28];
    const float* bn_m    = (const float*)d_in[29];
    const float* bn_v    = (const float*)d_in[30];
    float* out = (float*)d_out;

    void *pH, *pY1, *pY2, *pZ2, *pAS, *pAF, *pAB, *pWH, *pPS, *pPT;
    void *pAH, *pXH, *pY1H, *pY2H, *pZ2H, *pBH, *pQH, *pKH;
    cudaGetSymbolAddress(&pH,  g_h);
    cudaGetSymbolAddress(&pY1, g_y1);
    cudaGetSymbolAddress(&pY2, g_y2);
    cudaGetSymbolAddress(&pZ2, g_z2);
    cudaGetSymbolAddress(&pAS, g_atts);
    cudaGetSymbolAddress(&pAF, g_attf);
    cudaGetSymbolAddress(&pAB, g_attb);
    cudaGetSymbolAddress(&pPS, g_ps);
    cudaGetSymbolAddress(&pPT, g_pt);
    cudaGetSymbolAddress(&pWH, g_wh);
    cudaGetSymbolAddress(&pAH, g_ah);
    cudaGetSymbolAddress(&pXH, g_xh);
    cudaGetSymbolAddress(&pY1H, g_y1h);
    cudaGetSymbolAddress(&pY2H, g_y2h);
    cudaGetSymbolAddress(&pZ2H, g_z2h);
    cudaGetSymbolAddress(&pBH, g_bufBh);
    cudaGetSymbolAddress(&pQH, g_qh);
    cudaGetSymbolAddress(&pKH, g_kh);
    float* h    = (float*)pH;  float* y1   = (float*)pY1;
    float* y2   = (float*)pY2; float* z2b  = (float*)pZ2;
    float* atts = (float*)pAS; float* attf = (float*)pAF;
    float* attb = (float*)pAB;
    float* ps   = (float*)pPS; float* pt   = (float*)pPT;
    __half* wh   = (__half*)pWH;
    __half* ah   = (__half*)pAH;
    __half* xh   = (__half*)pXH;
    __half* y1h  = (__half*)pY1H;
    __half* y2h  = (__half*)pY2H;
    __half* z2h  = (__half*)pZ2H;
    __half* bufh = (__half*)pBH;
    __half* qh   = (__half*)pQH;
    __half* kh   = (__half*)pKH;

    cudaFuncSetAttribute(gemm_h, cudaFuncAttributeMaxDynamicSharedMemorySize, GSM);
    cudaFuncSetAttribute(conv_h, cudaFuncAttributeMaxDynamicSharedMemorySize, GSM);
    cudaFuncSetAttribute(z2k, cudaFuncAttributeMaxDynamicSharedMemorySize, (64*256 + 256) * 4);
    cudaFuncSetAttribute(deint_s2, cudaFuncAttributeMaxDynamicSharedMemorySize, DS_SMEM);
    cudaFuncSetAttribute(deint_t2, cudaFuncAttributeMaxDynamicSharedMemorySize, DT_SMEM);

    dim3 blk(256);
    const int MB = RTOT / 128;   // 400
    const int WHALF = WTOT / 2;

    prep_x<<<(XITEMS + 255) / 256, blk>>>(x, xh);
    prep_w<<<(WHALF + 255) / 256, blk>>>(Wqk_s, Wo_s, Wff_s, Wqk_t, Wo_t, Wff_t,
                                         conv_w, wh, 0, WHALF);
    prep_w<<<(WHALF + 255) / 256, blk>>>(Wqk_s, Wo_s, Wff_s, Wqk_t, Wo_t, Wff_t,
                                         conv_w, wh, WHALF, WTOT - WHALF);
    cudaMemsetAsync(ps, 0, 96 * 625 * sizeof(float));
    cudaMemsetAsync(pt, 0, 128 * 4096 * sizeof(float));

    // Stage 1: spatial
    gemm_h<<<dim3(3, MB), blk, GSM>>>(xh, wh + OFF_QKS, bqk_s, h, bufh, 1, RTOT, 384, 256);
    deint_s2<<<NN * VV * 2, blk, DS_SMEM>>>(bufh, qh, kh);
    att_s_part<<<dim3(96, 8), 128>>>(qh, kh, ps);
    att_s_fin<<<(96 * 625 + 255) / 256, blk>>>(ps, alphas, att0s, atts);
    ys2<<<NN * TT, blk>>>(x, atts, ah);
    gemm_h<<<dim3(2, MB), blk, GSM>>>(ah, wh + OFF_WOS, bo_s, h, bufh, 0, RTOT, 256, 768);
    ln2<<<NN*VV, blk>>>(h, x, g_os, b_os, y1, y1h, TT*256, 0, 0);
    gemm_h<<<dim3(2, MB), blk, GSM>>>(y1h, wh + OFF_FFS, bff_s, h, bufh, 0, RTOT, 256, 256);
    ln2<<<NN*VV, blk>>>(h, x, g_ffs, b_ffs, y2, y2h, TT*256, 1, 1);

    // Stage 2: temporal
    gemm_h<<<dim3(4, MB), blk, GSM>>>(y2h, wh + OFF_QKT, bqk_t, h, bufh, 1, RTOT, 512, 256);
    deint_t2<<<NN * TT, blk, DT_SMEM>>>(bufh, qh, kh);
    att_t_part<<<dim3(128, 5), blk>>>(qh, kh, pt);
    att_t_fin<<<(128 * 4096 + 255) / 256, blk>>>(pt, alphat_f, alphat_b, attf, attb);
    z2k<<<NN * VV, blk, (64*256 + 256) * 4>>>(y2, attf, attb, ah);
    gemm_h<<<dim3(2, MB), blk, GSM>>>(ah, wh + OFF_WOT, bo_t, h, bufh, 0, RTOT, 256, 1024);
    ln2<<<NN*TT, blk>>>(h, y2, g_ot, b_ot, y1, y1h, VV*256, 0, 0);
    gemm_h<<<dim3(2, MB), blk, GSM>>>(y1h, wh + OFF_FFT, bff_t, h, bufh, 0, RTOT, 256, 256);
    ln2<<<NN*TT, blk>>>(h, y2, g_fft, b_fft, z2b, z2h, VV*256, 0, 1);

    // Stage 3: conv + BN + gelu + residual + transpose (fused)
    conv_h<<<dim3(2, MB), blk, GSM>>>(z2h, wh + OFF_CNV, conv_b, z2b,
                                      bn_g, bn_b, bn_m, bn_v, out);
}

// round 17
// speedup vs baseline: 1.6314x; 1.2820x over previous
#include <cuda_runtime.h>
#include <cuda_fp16.h>
#include <math.h>
#include <stdint.h>

#define NN 32
#define VV 25
#define TT 64
#define RTOT (NN*VV*TT)   /* 51200 */

// ------------------------- scratch (device globals) -------------------------
__device__ float g_h   [(size_t)RTOT * 256];
__device__ float g_y1  [(size_t)RTOT * 256];
__device__ float g_y2  [(size_t)RTOT * 256];
__device__ float g_z2  [(size_t)RTOT * 256];
__device__ float g_atts[NN*VV*VV*3];
__device__ float g_ps  [96*625];
// fp16 buffers (16B-aligned for cp.async)
__device__ __align__(128) __half g_bufBh[(size_t)RTOT * 512];
__device__ __align__(128) __half g_qh [13107200];
__device__ __align__(128) __half g_kh [13107200];
__device__ __align__(128) __half g_ah [(size_t)RTOT * 1024];
__device__ __align__(128) __half g_xh [(size_t)RTOT * 256];
__device__ __align__(128) __half g_y1h[(size_t)RTOT * 256];
__device__ __align__(128) __half g_y2h[(size_t)RTOT * 256];
__device__ __align__(128) __half g_z2h[(size_t)RTOT * 256];
__device__ __align__(128) __half g_atth[128*64*64];
__device__ __align__(128) __half g_yth [13107200];
#define WTOT 1277952
__device__ __align__(128) __half g_wh[WTOT];
#define OFF_QKS 0         /* K=256  N=384  */
#define OFF_WOS 98304     /* K=768  N=256  */
#define OFF_FFS 294912    /* K=256  N=256  */
#define OFF_QKT 360448    /* K=256  N=512  */
#define OFF_WOT 491520    /* K=1024 N=256  */
#define OFF_FFT 753664    /* K=256  N=256  */
#define OFF_CNV 819200    /* K=1792 N=256  */

__device__ __forceinline__ float gelu_f(float x) {
    return 0.5f * x * (1.0f + erff(x * 0.7071067811865475f));
}
__device__ __forceinline__ uint32_t packh2(float a, float b) {
    __half2 h = __floats2half2_rn(a, b);
    return *(uint32_t*)&h;
}
__device__ __forceinline__ uint32_t smem_u32(const void* p) {
    uint32_t a;
    asm("{ .reg .u64 t; cvta.to.shared.u64 t, %1; cvt.u32.u64 %0, t; }" : "=r"(a) : "l"(p));
    return a;
}
__device__ __forceinline__ void ldm4(uint32_t &r0, uint32_t &r1, uint32_t &r2,
                                     uint32_t &r3, uint32_t a) {
    asm volatile("ldmatrix.sync.aligned.m8n8.x4.shared.b16 {%0,%1,%2,%3}, [%4];"
        : "=r"(r0), "=r"(r1), "=r"(r2), "=r"(r3) : "r"(a));
}
__device__ __forceinline__ void mma16816h(float* c, const uint32_t* a, const uint32_t* b) {
    asm volatile(
        "mma.sync.aligned.m16n8k16.row.col.f32.f16.f16.f32 "
        "{%0,%1,%2,%3}, {%4,%5,%6,%7}, {%8,%9}, {%0,%1,%2,%3};"
        : "+f"(c[0]), "+f"(c[1]), "+f"(c[2]), "+f"(c[3])
        : "r"(a[0]), "r"(a[1]), "r"(a[2]), "r"(a[3]), "r"(b[0]), "r"(b[1]));
}
__device__ __forceinline__ void cpa16(uint32_t dst, const void* src) {
    asm volatile("cp.async.cg.shared.global [%0], [%1], 16;" :: "r"(dst), "l"(src));
}
__device__ __forceinline__ void cpa16z(uint32_t dst, const void* src, int sz) {
    asm volatile("cp.async.cg.shared.global [%0], [%1], 16, %2;" :: "r"(dst), "l"(src), "r"(sz));
}
#define CPA_COMMIT() asm volatile("cp.async.commit_group;" ::: "memory")
#define CPA_WAIT1() asm volatile("cp.async.wait_group 1;" ::: "memory")
#define CPA_WAIT0() asm volatile("cp.async.wait_group 0;" ::: "memory")

// smem swizzle for 128B rows (64 fp16): 16B chunk ch of row r at (ch ^ (r&7))*16
#define SWZ8(row, ch) ((uint32_t)((row) * 128 + (((ch) ^ ((row) & 7)) << 4)))

// == fp16 HMMA GEMM (single-term): 128x128 tile, warp 64x32, k-chunk 64 ======
#define GSM (2*32768)
__global__ __launch_bounds__(256, 2) void gemm_h(
        const __half* __restrict__ A, const __half* __restrict__ B,
        const float* __restrict__ bias, float* __restrict__ Cf,
        __half* __restrict__ Ch, int h16, int M, int N, int K) {
    extern __shared__ char sm[];
    const uint32_t sbase = smem_u32(sm);
    const int tid = threadIdx.x, lane = tid & 31, w = tid >> 5;
    const int wm = w & 1, wn = w >> 1;
    const int bm = blockIdx.y << 7, bn = blockIdx.x << 7;
    float acc[4][4][4];
#pragma unroll
    for (int i = 0; i < 4; i++)
#pragma unroll
        for (int j = 0; j < 4; j++)
#pragma unroll
            for (int q = 0; q < 4; q++) acc[i][j][q] = 0.f;
    const int nch = K >> 6;

    auto load_stage = [&](int c) {
        uint32_t st = sbase + (c & 1) * 32768;
        const int k0 = c << 6;
#pragma unroll
        for (int j = 0; j < 4; j++) {
            int f = j * 256 + tid;
            int row = f >> 3, ch = f & 7;
            uint32_t off = SWZ8(row, ch);
            cpa16(st + off,         A + (size_t)(bm + row) * K + k0 + ch * 8);
            cpa16(st + 16384 + off, B + (size_t)(bn + row) * K + k0 + ch * 8);
        }
        CPA_COMMIT();
    };
    load_stage(0);
    for (int c = 0; c < nch; c++) {
        if (c + 1 < nch) { load_stage(c + 1); CPA_WAIT1(); }
        else CPA_WAIT0();
        __syncthreads();
        const uint32_t sA = sbase + (c & 1) * 32768;
        const uint32_t sB = sA + 16384;
#pragma unroll
        for (int kk = 0; kk < 4; kk++) {
            uint32_t af[4][4];
            const int arow = wm * 64 + (lane & 15);
            const int achunk = kk * 2 + (lane >> 4);
#pragma unroll
            for (int mi = 0; mi < 4; mi++) {
                int row = arow + mi * 16;
                ldm4(af[mi][0], af[mi][1], af[mi][2], af[mi][3], sA + SWZ8(row, achunk));
            }
            const int bchunk = kk * 2 + ((lane >> 3) & 1);
            uint32_t bf[4][2];
#pragma unroll
            for (int ng = 0; ng < 2; ng++) {
                int brow = wn * 32 + ng * 16 + ((lane & 16) >> 1) + (lane & 7);
                ldm4(bf[2*ng][0], bf[2*ng][1], bf[2*ng+1][0], bf[2*ng+1][1],
                     sB + SWZ8(brow, bchunk));
            }
#pragma unroll
            for (int mi = 0; mi < 4; mi++)
#pragma unroll
                for (int nf = 0; nf < 4; nf++)
                    mma16816h(acc[mi][nf], af[mi], bf[nf]);
        }
        __syncthreads();
    }
    const int gid = lane >> 2, tig = lane & 3;
#pragma unroll
    for (int mi = 0; mi < 4; mi++)
#pragma unroll
        for (int nf = 0; nf < 4; nf++) {
            int col = bn + wn * 32 + nf * 8 + tig * 2;
            float b0v = bias[col], b1v = bias[col + 1];
            int r0 = bm + wm * 64 + mi * 16 + gid;
            if (h16) {
                *(uint32_t*)(Ch + (size_t)r0 * N + col) =
                    packh2(acc[mi][nf][0] + b0v, acc[mi][nf][1] + b1v);
                *(uint32_t*)(Ch + (size_t)(r0 + 8) * N + col) =
                    packh2(acc[mi][nf][2] + b0v, acc[mi][nf][3] + b1v);
            } else {
                *(float2*)(Cf + (size_t)r0 * N + col) =
                    make_float2(acc[mi][nf][0] + b0v, acc[mi][nf][1] + b1v);
                *(float2*)(Cf + (size_t)(r0 + 8) * N + col) =
                    make_float2(acc[mi][nf][2] + b0v, acc[mi][nf][3] + b1v);
            }
        }
}

// == conv + BN + gelu + residual + transpose fused: K=1792, warp 64x32 =======
__global__ __launch_bounds__(256, 2) void conv_h(
        const __half* __restrict__ Z, const __half* __restrict__ B,
        const float* __restrict__ cbias, const float* __restrict__ z2,
        const float* __restrict__ bng, const float* __restrict__ bnb,
        const float* __restrict__ bnm, const float* __restrict__ bnv,
        float* __restrict__ out) {
    const int N = 256, K = 1792;
    extern __shared__ char sm[];
    const uint32_t sbase = smem_u32(sm);
    const int tid = threadIdx.x, lane = tid & 31, w = tid >> 5;
    const int wm = w & 1, wn = w >> 1;
    const int bm = blockIdx.y << 7, bn = blockIdx.x << 7;
    float acc[4][4][4];
#pragma unroll
    for (int i = 0; i < 4; i++)
#pragma unroll
        for (int j = 0; j < 4; j++)
#pragma unroll
            for (int q = 0; q < 4; q++) acc[i][j][q] = 0.f;
    const int nch = K >> 6;   // 28

    auto load_stage = [&](int c) {
        uint32_t st = sbase + (c & 1) * 32768;
        const int k0 = c << 6;
        const int dt = (k0 >> 8) - 3;
        const int iio = k0 & 255;
#pragma unroll
        for (int j = 0; j < 4; j++) {
            int f = j * 256 + tid;
            int row = f >> 3, ch = f & 7;
            uint32_t off = SWZ8(row, ch);
            int grow = bm + row;
            int t = (grow / VV) % TT;
            int tt = t + dt;
            int ok = (tt >= 0 && tt < TT);
            size_t srcoff = ok ? ((size_t)grow + (size_t)dt * VV) * 256 + iio + ch * 8 : 0;
            cpa16z(st + off, Z + srcoff, ok ? 16 : 0);
            cpa16(st + 16384 + off, B + (size_t)(bn + row) * K + k0 + ch * 8);
        }
        CPA_COMMIT();
    };
    load_stage(0);
    for (int c = 0; c < nch; c++) {
        if (c + 1 < nch) { load_stage(c + 1); CPA_WAIT1(); }
        else CPA_WAIT0();
        __syncthreads();
        const uint32_t sA = sbase + (c & 1) * 32768;
        const uint32_t sB = sA + 16384;
#pragma unroll
        for (int kk = 0; kk < 4; kk++) {
            uint32_t af[4][4];
            const int arow = wm * 64 + (lane & 15);
            const int achunk = kk * 2 + (lane >> 4);
#pragma unroll
            for (int mi = 0; mi < 4; mi++) {
                int row = arow + mi * 16;
                ldm4(af[mi][0], af[mi][1], af[mi][2], af[mi][3], sA + SWZ8(row, achunk));
            }
            const int bchunk = kk * 2 + ((lane >> 3) & 1);
            uint32_t bf[4][2];
#pragma unroll
            for (int ng = 0; ng < 2; ng++) {
                int brow = wn * 32 + ng * 16 + ((lane & 16) >> 1) + (lane & 7);
                ldm4(bf[2*ng][0], bf[2*ng][1], bf[2*ng+1][0], bf[2*ng+1][1],
                     sB + SWZ8(brow, bchunk));
            }
#pragma unroll
            for (int mi = 0; mi < 4; mi++)
#pragma unroll
                for (int nf = 0; nf < 4; nf++)
                    mma16816h(acc[mi][nf], af[mi], bf[nf]);
        }
        __syncthreads();
    }
    const int gid = lane >> 2, tig = lane & 3;
#pragma unroll
    for (int mi = 0; mi < 4; mi++)
#pragma unroll
        for (int nf = 0; nf < 4; nf++) {
            int col = bn + wn * 32 + nf * 8 + tig * 2;
            float cb0 = cbias[col], cb1 = cbias[col + 1];
            float s0 = rsqrtf(bnv[col] + 1e-5f) * bng[col];
            float s1 = rsqrtf(bnv[col + 1] + 1e-5f) * bng[col + 1];
            float m0 = bnm[col], m1 = bnm[col + 1];
            float bb0 = bnb[col], bb1 = bnb[col + 1];
#pragma unroll
            for (int rr = 0; rr < 2; rr++) {
                int grow = bm + wm * 64 + mi * 16 + gid + rr * 8;
                int n = grow / (TT * VV);
                int rem = grow - n * TT * VV;
                int t = rem / VV, v = rem - t * VV;
                float z0 = z2[(size_t)grow * 256 + col];
                float z1 = z2[(size_t)grow * 256 + col + 1];
                float a0 = acc[mi][nf][rr * 2 + 0], a1 = acc[mi][nf][rr * 2 + 1];
                float c0 = fmaf(a0 + cb0 - m0, s0, bb0);
                float c1 = fmaf(a1 + cb1 - m1, s1, bb1);
                *(float2*)(out + ((size_t)(n * VV + v) * TT + t) * 256 + col) =
                    make_float2(gelu_f(z0 + c0), gelu_f(z1 + c1));
            }
        }
}

// == att_t2: per (n,m) 64x64xK=1600 MMA; fused tanh*alpha*mask; fp16 out =====
#define ATSM (2*16384)
__global__ __launch_bounds__(256, 2) void att_t2(
        const __half* __restrict__ qd, const __half* __restrict__ kd,
        const float* __restrict__ alf, const float* __restrict__ alb,
        __half* __restrict__ atth) {
    extern __shared__ char sm[];
    const uint32_t sbase = smem_u32(sm);
    const int nm = blockIdx.x;
    const int m = nm & 3, dir = m >> 1, s = m & 1;
    const float alpha = dir ? alb[s] : alf[s];
    const __half* A = kd + (size_t)nm * 102400;   // rows -> output q
    const __half* Bq = qd + (size_t)nm * 102400;  // rows -> output t
    const int tid = threadIdx.x, lane = tid & 31, w = tid >> 5;
    const int wq = w & 3, wt = w >> 2;
    float acc[4][4] = {};
    auto load_stage = [&](int c) {
        uint32_t st = sbase + (c & 1) * 16384;
        const int k0 = c * 64;
#pragma unroll
        for (int j = 0; j < 2; j++) {
            int f = j * 256 + tid;
            int row = f >> 3, ch = f & 7;
            cpa16(st + SWZ8(row, ch),        A  + (size_t)row * 1600 + k0 + ch * 8);
            cpa16(st + 8192 + SWZ8(row, ch), Bq + (size_t)row * 1600 + k0 + ch * 8);
        }
        CPA_COMMIT();
    };
    load_stage(0);
    for (int c = 0; c < 25; c++) {
        if (c + 1 < 25) { load_stage(c + 1); CPA_WAIT1(); }
        else CPA_WAIT0();
        __syncthreads();
        const uint32_t sA = sbase + (c & 1) * 16384, sB = sA + 8192;
#pragma unroll
        for (int kk = 0; kk < 4; kk++) {
            uint32_t af[4];
            int arow = wq * 16 + (lane & 15);
            int achunk = kk * 2 + (lane >> 4);
            ldm4(af[0], af[1], af[2], af[3], sA + SWZ8(arow, achunk));
            int bchunk = kk * 2 + ((lane >> 3) & 1);
            uint32_t bf[4][2];
#pragma unroll
            for (int ng = 0; ng < 2; ng++) {
                int brow = wt * 32 + ng * 16 + ((lane & 16) >> 1) + (lane & 7);
                ldm4(bf[2*ng][0], bf[2*ng][1], bf[2*ng+1][0], bf[2*ng+1][1],
                     sB + SWZ8(brow, bchunk));
            }
#pragma unroll
            for (int nf = 0; nf < 4; nf++)
                mma16816h(acc[nf], af, bf[nf]);
        }
        __syncthreads();
    }
    const int gid = lane >> 2, tig = lane & 3;
#pragma unroll
    for (int nf = 0; nf < 4; nf++) {
        int t0 = wt * 32 + nf * 8 + tig * 2;
#pragma unroll
        for (int rr = 0; rr < 2; rr++) {
            int q = wq * 16 + gid + rr * 8;
            float v0 = tanhf(acc[nf][rr * 2 + 0] * (1.f / 1600.f)) * alpha;
            float v1 = tanhf(acc[nf][rr * 2 + 1] * (1.f / 1600.f)) * alpha;
            bool m0 = dir ? (q >= t0) : (q <= t0);
            bool m1 = dir ? (q >= t0 + 1) : (q <= t0 + 1);
            *(uint32_t*)(atth + ((size_t)nm * 64 + q) * 64 + t0) =
                packh2(m0 ? v0 : 0.f, m1 ? v1 : 0.f);
        }
    }
}

// == ytr: transpose y2h (n,t,v,c) -> yT (n,v)(c)(t) fp16 =====================
__global__ __launch_bounds__(256) void ytr(const __half* __restrict__ y2h,
                                           __half* __restrict__ yT) {
    __shared__ __half smy[64][260];
    int b = blockIdx.x;
    int n = b / VV, v = b % VV;
    for (int i = threadIdx.x; i < 64 * 128; i += 256) {
        int idx = i * 2;
        int t = idx >> 8, c = idx & 255;
        *(uint32_t*)&smy[t][c] =
            *(const uint32_t*)(y2h + ((size_t)(n * TT + t) * VV + v) * 256 + c);
    }
    __syncthreads();
    int c = threadIdx.x;
    __half* dst = yT + ((size_t)(n * VV + v) * 256 + c) * 64;
#pragma unroll
    for (int t = 0; t < 64; t += 2) {
        uint32_t lo = __half_as_ushort(smy[t][c]);
        uint32_t hi = __half_as_ushort(smy[t + 1][c]);
        *(uint32_t*)(dst + t) = lo | (hi << 16);
    }
}

// == zmm: Z_p[q,c] = att_p[q,:] @ yT[:,c], K=64, 4 planes; fp16 out ==========
#define ZSM (4*8192 + 16384)
__global__ __launch_bounds__(256, 2) void zmm(
        const __half* __restrict__ atth, const __half* __restrict__ yT,
        __half* __restrict__ zh) {
    extern __shared__ char sm[];
    const uint32_t sbase = smem_u32(sm);
    int b = blockIdx.x;
    int half = b & 1, nv = b >> 1;
    int n = nv / VV, v = nv % VV;
    const int tid = threadIdx.x, lane = tid & 31, w = tid >> 5;
    const int p = w >> 1, qh = w & 1;
    // load 4 att planes (4 x 64 rows x 8 chunks)
#pragma unroll
    for (int j = 0; j < 8; j++) {
        int f = j * 256 + tid;
        int pp = f >> 9, r = f & 511;
        int row = r >> 3, ch = r & 7;
        cpa16(sbase + pp * 8192 + SWZ8(row, ch),
              atth + ((size_t)(n * 4 + pp) * 64 + row) * 64 + ch * 8);
    }
    // load yT half (128 rows x 8 chunks)
#pragma unroll
    for (int j = 0; j < 4; j++) {
        int f = j * 256 + tid;
        int row = f >> 3, ch = f & 7;
        cpa16(sbase + 32768 + SWZ8(row, ch),
              yT + ((size_t)(n * VV + v) * 256 + half * 128 + row) * 64 + ch * 8);
    }
    CPA_COMMIT(); CPA_WAIT0();
    __syncthreads();
    const uint32_t sA = sbase + p * 8192, sB = sbase + 32768;
    uint32_t af[2][4][4];
#pragma unroll
    for (int mi = 0; mi < 2; mi++)
#pragma unroll
        for (int kk = 0; kk < 4; kk++) {
            int arow = qh * 32 + mi * 16 + (lane & 15);
            int achunk = kk * 2 + (lane >> 4);
            ldm4(af[mi][kk][0], af[mi][kk][1], af[mi][kk][2], af[mi][kk][3],
                 sA + SWZ8(arow, achunk));
        }
    const int gid = lane >> 2, tig = lane & 3;
#pragma unroll
    for (int ci = 0; ci < 4; ci++) {
        float acc[2][4][4];
#pragma unroll
        for (int i = 0; i < 2; i++)
#pragma unroll
            for (int j = 0; j < 4; j++)
#pragma unroll
                for (int q = 0; q < 4; q++) acc[i][j][q] = 0.f;
#pragma unroll
        for (int kk = 0; kk < 4; kk++) {
            int bchunk = kk * 2 + ((lane >> 3) & 1);
            uint32_t bf[4][2];
#pragma unroll
            for (int ng = 0; ng < 2; ng++) {
                int brow = ci * 32 + ng * 16 + ((lane & 16) >> 1) + (lane & 7);
                ldm4(bf[2*ng][0], bf[2*ng][1], bf[2*ng+1][0], bf[2*ng+1][1],
                     sB + SWZ8(brow, bchunk));
            }
#pragma unroll
            for (int mi = 0; mi < 2; mi++)
#pragma unroll
                for (int nf = 0; nf < 4; nf++)
                    mma16816h(acc[mi][nf], af[mi][kk], bf[nf]);
        }
#pragma unroll
        for (int mi = 0; mi < 2; mi++)
#pragma unroll
            for (int nf = 0; nf < 4; nf++)
#pragma unroll
                for (int rr = 0; rr < 2; rr++) {
                    int q = qh * 32 + mi * 16 + gid + rr * 8;
                    int cl = half * 128 + ci * 32 + nf * 8 + tig * 2;
                    size_t rowi = ((size_t)(n * TT + q) * VV + v);
                    *(uint32_t*)(zh + rowi * 1024 + p * 256 + cl) =
                        packh2(acc[mi][nf][rr * 2], acc[mi][nf][rr * 2 + 1]);
                }
    }
}

// ---------------- prep kernels (x convert; weight fp16 transpose) -----------
#define XITEMS 3276800
__global__ void prep_x(const float* __restrict__ x, __half* __restrict__ xh) {
    size_t idx = (size_t)blockIdx.x * 256 + threadIdx.x;
    if (idx >= XITEMS) return;
    size_t i = idx * 4;
    float4 v = *(const float4*)(x + i);
    *(uint2*)(xh + i) = make_uint2(packh2(v.x, v.y), packh2(v.z, v.w));
}
__global__ void prep_w(
        const float* __restrict__ Wqks, const float* __restrict__ Wos,
        const float* __restrict__ Wffs, const float* __restrict__ Wqkt,
        const float* __restrict__ Wot,  const float* __restrict__ Wfft,
        const float* __restrict__ Wcnv,
        __half* __restrict__ wh, int jbase, int jcount) {
    int li = blockIdx.x * 256 + threadIdx.x;
    if (li >= jcount) return;
    long j = (long)jbase + li;
    const float* W; int K, N, off; int isconv = 0, iswot = 0;
    if (j < 98304)                    { W = Wqks; K = 256;  N = 384; off = OFF_QKS; }
    else if ((j -= 98304)  < 196608)  { W = Wos;  K = 768;  N = 256; off = OFF_WOS; }
    else if ((j -= 196608) < 65536)   { W = Wffs; K = 256;  N = 256; off = OFF_FFS; }
    else if ((j -= 65536)  < 131072)  { W = Wqkt; K = 256;  N = 512; off = OFF_QKT; }
    else if ((j -= 131072) < 262144)  { W = Wot;  K = 1024; N = 256; off = OFF_WOT; iswot = 1; }
    else if ((j -= 262144) < 65536)   { W = Wfft; K = 256;  N = 256; off = OFF_FFT; }
    else if ((j -= 65536)  < 458752)  { W = Wcnv; K = 1792; N = 256; off = OFF_CNV; isconv = 1; }
    else return;
    float v = W[j];
    size_t dst;
    if (isconv) {
        int o = (int)(j / 1792), r = (int)(j % 1792);
        int ii = r / 7, kw = r % 7;
        dst = (size_t)off + (size_t)o * 1792 + kw * 256 + ii;
    } else {
        int k = (int)(j / N), n = (int)(j % N);
        if (iswot) {   // z plane-major layout: k_new = dir*512 + s*256 + c
            int dir = k >> 9, r = k & 511, cc = r >> 1, ss = r & 1;
            k = (dir << 9) + (ss << 8) + cc;
        }
        dst = (size_t)off + (size_t)n * K + k;
    }
    wh[dst] = __float2half(v);
}

// ------ deint_s: fp16 in/out, smem-staged. block per (n,u,t-half) -----------
#define DS_SMEM (6 * 2056 * 2)
__global__ __launch_bounds__(256) void deint_s2(const __half* __restrict__ qk,
                                                __half* __restrict__ qT,
                                                __half* __restrict__ kT) {
    extern __shared__ __half smsh[];
    int b = blockIdx.x;
    int th = b & 1;
    int u = (b >> 1) % VV;
    int n = b / (VV * 2);
    int t0 = th << 5;
    const __half* src = qk + ((size_t)(n * VV + u) * TT + t0) * 384;
    for (int i = threadIdx.x; i < 32 * 384; i += 256) {
        int tt = i / 384, col = i % 384;
        int ci = col / 6, r = col % 6;
        smsh[r * 2056 + tt * 64 + ci] = src[i];
    }
    __syncthreads();
#pragma unroll
    for (int p = 0; p < 6; p++) {
        int s = (p < 3) ? p : p - 3;
        __half* dst = ((p < 3) ? qT : kT) +
                      (((size_t)(n * 3 + s) * VV + u) << 12) + (size_t)t0 * 64;
        for (int i = threadIdx.x; i < 2048; i += 256)
            dst[i] = smsh[p * 2056 + i];
    }
}

// ------ deint_t: fp16 in/out, smem-staged. block per (n,t) -------------------
#define DT_SMEM (8 * 1672 * 2)
__global__ __launch_bounds__(256) void deint_t2(const __half* __restrict__ qkt,
                                                __half* __restrict__ qd,
                                                __half* __restrict__ kd) {
    extern __shared__ __half smth[];
    int b = blockIdx.x;
    int t = b % TT, n = b / TT;
    const __half* src = qkt + ((size_t)(n * TT + t) * VV) * 512;
    for (int i = threadIdx.x; i < 25 * 512; i += 256) {
        int v = i >> 9, col = i & 511;
        int ci = col >> 3, j = col & 7;
        smth[j * 1672 + v * 64 + ci] = src[i];
    }
    __syncthreads();
#pragma unroll
    for (int p = 0; p < 8; p++) {
        int m = p & 3;
        __half* dst = ((p < 4) ? qd : kd) + ((size_t)(n * 4 + m) * TT + t) * 1600;
        for (int i = threadIdx.x; i < 1600; i += 256)
            dst[i] = smth[p * 1672 + i];
    }
}

// spatial attention split-K partials (fp16 inputs)
__global__ __launch_bounds__(128) void att_s_part(
        const __half* __restrict__ qT, const __half* __restrict__ kT,
        float* __restrict__ ps) {
    int ns = blockIdx.x;
    int kc0 = blockIdx.y << 9;
    __shared__ float qs[25][132], ks[25][132];
    const __half* qb = qT + ((size_t)ns * VV << 12);
    const __half* kb = kT + ((size_t)ns * VV << 12);
    int t = threadIdx.x;
    int u0 = (t / 25) * 5, v = t % 25;
    float acc[5] = {0.f, 0.f, 0.f, 0.f, 0.f};
    for (int kc = kc0; kc < kc0 + 512; kc += 128) {
        for (int i = t; i < 25 * 128; i += 128) {
            int uu = i >> 7, e = i & 127;
            qs[uu][e] = __half2float(qb[((size_t)uu << 12) + kc + e]);
            ks[uu][e] = __half2float(kb[((size_t)uu << 12) + kc + e]);
        }
        __syncthreads();
        if (t < 125) {
#pragma unroll 4
            for (int e = 0; e < 128; e++) {
                float kv = ks[v][e];
                acc[0] = fmaf(qs[u0 + 0][e], kv, acc[0]);
                acc[1] = fmaf(qs[u0 + 1][e], kv, acc[1]);
                acc[2] = fmaf(qs[u0 + 2][e], kv, acc[2]);
                acc[3] = fmaf(qs[u0 + 3][e], kv, acc[3]);
                acc[4] = fmaf(qs[u0 + 4][e], kv, acc[4]);
            }
        }
        __syncthreads();
    }
    if (t < 125) {
#pragma unroll
        for (int i = 0; i < 5; i++)
            atomicAdd(&ps[(size_t)ns * 625 + (u0 + i) * 25 + v], acc[i]);
    }
}

__global__ void att_s_fin(const float* __restrict__ ps, const float* __restrict__ alphas,
                          const float* __restrict__ att0, float* __restrict__ att) {
    int idx = blockIdx.x * 256 + threadIdx.x;
    if (idx >= 96 * 625) return;
    int ns = idx / 625, r = idx % 625;
    int n = ns / 3, s = ns % 3, u = r / 25, v = r % 25;
    att[((size_t)(n * VV + u) * VV + v) * 3 + s] =
        tanhf(ps[idx] * (1.f / 4096.f)) * alphas[s] + att0[((size_t)u * VV + v) * 3 + s];
}

// y_s: block per (n,t); fp16 output
__global__ __launch_bounds__(256) void ys2(const float* __restrict__ x,
                                           const float* __restrict__ att,
                                           __half* __restrict__ yh) {
    __shared__ float xs[25][256];
    __shared__ float as_[25 * 25 * 3];
    int b = blockIdx.x;
    int n = b >> 6, t = b & 63;
    int tid = threadIdx.x;
    for (int i = tid; i < 25 * 256; i += 256) {
        int u = i >> 8, c = i & 255;
        xs[u][c] = x[((size_t)(n * VV + u) * TT + t) * 256 + c];
    }
    for (int i = tid; i < 1875; i += 256) as_[i] = att[(size_t)n * 1875 + i];
    __syncthreads();
    int c = tid;
#pragma unroll 1
    for (int v = 0; v < VV; v++) {
        float a0 = 0.f, a1 = 0.f, a2 = 0.f;
#pragma unroll
        for (int u = 0; u < VV; u++) {
            float xv = xs[u][c];
            a0 = fmaf(xv, as_[(u * VV + v) * 3 + 0], a0);
            a1 = fmaf(xv, as_[(u * VV + v) * 3 + 1], a1);
            a2 = fmaf(xv, as_[(u * VV + v) * 3 + 2], a2);
        }
        size_t base = ((size_t)(n * VV + v) * TT + t) * 768 + c * 3;
        yh[base]     = __float2half(a0);
        yh[base + 1] = __float2half(a1);
        yh[base + 2] = __float2half(a2);
    }
}

// LN + residual + gelu; writes fp16 (+ optional fp32)
__global__ void ln2(const float* __restrict__ h, const float* __restrict__ res,
                    const float* __restrict__ g, const float* __restrict__ b,
                    float* __restrict__ outf, __half* __restrict__ oh,
                    int G, int mode, int wf) {
    int grp = blockIdx.x;
    const float* hp = h + (size_t)grp * G;
    const float* rp = res + (size_t)grp * G;
    float s = 0.f, sq = 0.f;
    for (int i = threadIdx.x; i < G; i += blockDim.x) {
        float v = hp[i]; s += v; sq = fmaf(v, v, sq);
    }
    for (int o = 16; o; o >>= 1) {
        s += __shfl_down_sync(0xffffffffu, s, o);
        sq += __shfl_down_sync(0xffffffffu, sq, o);
    }
    __shared__ float ss[8], sqs[8];
    __shared__ float mean_s, inv_s;
    int w = threadIdx.x >> 5;
    if ((threadIdx.x & 31) == 0) { ss[w] = s; sqs[w] = sq; }
    __syncthreads();
    if (threadIdx.x == 0) {
        float S = 0.f, Q = 0.f;
        for (int i = 0; i < 8; i++) { S += ss[i]; Q += sqs[i]; }
        float mean = S / G;
        float var = Q / G - mean * mean;
        mean_s = mean; inv_s = rsqrtf(var + 1e-5f);
    }
    __syncthreads();
    float mean = mean_s, inv = inv_s;
    int n = 0, v = 0;
    if (mode == 1) { n = grp / VV; v = grp % VV; }
    for (int i = threadIdx.x; i < G; i += blockDim.x) {
        float val = gelu_f(rp[i] + fmaf((hp[i] - mean) * inv, g[i], b[i]));
        size_t dst;
        if (mode == 0) dst = (size_t)grp * G + i;
        else {
            int t = i >> 8, c = i & 255;
            dst = ((size_t)(n * TT + t) * VV + v) * 256 + c;
        }
        if (wf) outf[dst] = val;
        oh[dst] = __float2half(val);
    }
}

// ------------------------------- launcher -----------------------------------
extern "C" void kernel_launch(void* const* d_in, const int* in_sizes, int n_in,
                              void* d_out, int out_size) {
    const float* x       = (const float*)d_in[0];
    const float* Wqk_s   = (const float*)d_in[1];
    const float* bqk_s   = (const float*)d_in[2];
    const float* alphas  = (const float*)d_in[3];
    const float* att0s   = (const float*)d_in[4];
    const float* Wo_s    = (const float*)d_in[5];
    const float* bo_s    = (const float*)d_in[6];
    const float* g_os    = (const float*)d_in[7];
    const float* b_os    = (const float*)d_in[8];
    const float* Wff_s   = (const float*)d_in[9];
    const float* bff_s   = (const float*)d_in[10];
    const float* g_ffs   = (const float*)d_in[11];
    const float* b_ffs   = (const float*)d_in[12];
    const float* Wqk_t   = (const float*)d_in[13];
    const float* bqk_t   = (const float*)d_in[14];
    const float* alphat_f= (const float*)d_in[15];
    const float* alphat_b= (const float*)d_in[16];
    const float* Wo_t    = (const float*)d_in[17];
    const float* bo_t    = (const float*)d_in[18];
    const float* g_ot    = (const float*)d_in[19];
    const float* b_ot    = (const float*)d_in[20];
    const float* Wff_t   = (const float*)d_in[21];
    const float* bff_t   = (const float*)d_in[22];
    const float* g_fft   = (const float*)d_in[23];
    const float* b_fft   = (const float*)d_in[24];
    const float* conv_w  = (const float*)d_in[25];
    const float* conv_b  = (const float*)d_in[26];
    const float* bn_g    = (const float*)d_in[27];
    const float* bn_b    = (const float*)d_in[28];
    const float* bn_m    = (const float*)d_in[29];
    const float* bn_v    = (const float*)d_in[30];
    float* out = (float*)d_out;

    void *pH, *pY1, *pY2, *pZ2, *pAS, *pWH, *pPS;
    void *pAH, *pXH, *pY1H, *pY2H, *pZ2H, *pBH, *pQH, *pKH, *pATH, *pYT;
    cudaGetSymbolAddress(&pH,  g_h);
    cudaGetSymbolAddress(&pY1, g_y1);
    cudaGetSymbolAddress(&pY2, g_y2);
    cudaGetSymbolAddress(&pZ2, g_z2);
    cudaGetSymbolAddress(&pAS, g_atts);
    cudaGetSymbolAddress(&pPS, g_ps);
    cudaGetSymbolAddress(&pWH, g_wh);
    cudaGetSymbolAddress(&pAH, g_ah);
    cudaGetSymbolAddress(&pXH, g_xh);
    cudaGetSymbolAddress(&pY1H, g_y1h);
    cudaGetSymbolAddress(&pY2H, g_y2h);
    cudaGetSymbolAddress(&pZ2H, g_z2h);
    cudaGetSymbolAddress(&pBH, g_bufBh);
    cudaGetSymbolAddress(&pQH, g_qh);
    cudaGetSymbolAddress(&pKH, g_kh);
    cudaGetSymbolAddress(&pATH, g_atth);
    cudaGetSymbolAddress(&pYT, g_yth);
    float* h    = (float*)pH;  float* y1   = (float*)pY1;
    float* y2   = (float*)pY2; float* z2b  = (float*)pZ2;
    float* atts = (float*)pAS; float* ps   = (float*)pPS;
    __half* wh   = (__half*)pWH;
    __half* ah   = (__half*)pAH;
    __half* xh   = (__half*)pXH;
    __half* y1h  = (__half*)pY1H;
    __half* y2h  = (__half*)pY2H;
    __half* z2h  = (__half*)pZ2H;
    __half* bufh = (__half*)pBH;
    __half* qh   = (__half*)pQH;
    __half* kh   = (__half*)pKH;
    __half* atth = (__half*)pATH;
    __half* yt   = (__half*)pYT;

    cudaFuncSetAttribute(gemm_h, cudaFuncAttributeMaxDynamicSharedMemorySize, GSM);
    cudaFuncSetAttribute(conv_h, cudaFuncAttributeMaxDynamicSharedMemorySize, GSM);
    cudaFuncSetAttribute(att_t2, cudaFuncAttributeMaxDynamicSharedMemorySize, ATSM);
    cudaFuncSetAttribute(zmm, cudaFuncAttributeMaxDynamicSharedMemorySize, ZSM);
    cudaFuncSetAttribute(deint_s2, cudaFuncAttributeMaxDynamicSharedMemorySize, DS_SMEM);
    cudaFuncSetAttribute(deint_t2, cudaFuncAttributeMaxDynamicSharedMemorySize, DT_SMEM);

    dim3 blk(256);
    const int MB = RTOT / 128;   // 400
    const int WHALF = WTOT / 2;

    prep_x<<<(XITEMS + 255) / 256, blk>>>(x, xh);
    prep_w<<<(WHALF + 255) / 256, blk>>>(Wqk_s, Wo_s, Wff_s, Wqk_t, Wo_t, Wff_t,
                                         conv_w, wh, 0, WHALF);
    prep_w<<<(WHALF + 255) / 256, blk>>>(Wqk_s, Wo_s, Wff_s, Wqk_t, Wo_t, Wff_t,
                                         conv_w, wh, WHALF, WTOT - WHALF);
    cudaMemsetAsync(ps, 0, 96 * 625 * sizeof(float));

    // Stage 1: spatial
    gemm_h<<<dim3(3, MB), blk, GSM>>>(xh, wh + OFF_QKS, bqk_s, h, bufh, 1, RTOT, 384, 256);
    deint_s2<<<NN * VV * 2, blk, DS_SMEM>>>(bufh, qh, kh);
    att_s_part<<<dim3(96, 8), 128>>>(qh, kh, ps);
    att_s_fin<<<(96 * 625 + 255) / 256, blk>>>(ps, alphas, att0s, atts);
    ys2<<<NN * TT, blk>>>(x, atts, ah);
    gemm_h<<<dim3(2, MB), blk, GSM>>>(ah, wh + OFF_WOS, bo_s, h, bufh, 0, RTOT, 256, 768);
    ln2<<<NN*VV, blk>>>(h, x, g_os, b_os, y1, y1h, TT*256, 0, 0);
    gemm_h<<<dim3(2, MB), blk, GSM>>>(y1h, wh + OFF_FFS, bff_s, h, bufh, 0, RTOT, 256, 256);
    ln2<<<NN*VV, blk>>>(h, x, g_ffs, b_ffs, y2, y2h, TT*256, 1, 1);
    ytr<<<NN * VV, blk>>>(y2h, yt);

    // Stage 2: temporal
    gemm_h<<<dim3(4, MB), blk, GSM>>>(y2h, wh + OFF_QKT, bqk_t, h, bufh, 1, RTOT, 512, 256);
    deint_t2<<<NN * TT, blk, DT_SMEM>>>(bufh, qh, kh);
    att_t2<<<NN * 4, blk, ATSM>>>(qh, kh, alphat_f, alphat_b, atth);
    zmm<<<NN * VV * 2, blk, ZSM>>>(atth, yt, ah);
    gemm_h<<<dim3(2, MB), blk, GSM>>>(ah, wh + OFF_WOT, bo_t, h, bufh, 0, RTOT, 256, 1024);
    ln2<<<NN*TT, blk>>>(h, y2, g_ot, b_ot, y1, y1h, VV*256, 0, 0);
    gemm_h<<<dim3(2, MB), blk, GSM>>>(y1h, wh + OFF_FFT, bff_t, h, bufh, 0, RTOT, 256, 256);
    ln2<<<NN*TT, blk>>>(h, y2, g_fft, b_fft, z2b, z2h, VV*256, 0, 1);

    // Stage 3: conv + BN + gelu + residual + transpose (fused)
    conv_h<<<dim3(2, MB), blk, GSM>>>(z2h, wh + OFF_CNV, conv_b, z2b,
                                      bn_g, bn_b, bn_m, bn_v, out);
}